// round 2
// baseline (speedup 1.0000x reference)
#include <cuda_runtime.h>
#include <math.h>

#define TSEQ   2048
#define NH     16
#define DNOPE  128
#define DROPE  64
#define DQK    192
#define DLORA  512
#define DV     128
// 1/sqrt(192)
#define SCALE  0.07216878364870323f

// 16 MB scratch for k_nope[t][h][d]  (device global: allocation-free)
__device__ float g_knope[(size_t)TSEQ * NH * DNOPE];

// ---------------------------------------------------------------------------
// Kernel 1: k_nope[t, h, d] = sum_l k_c[t, l] * w_kv_b[l, h*256 + d], d<128
// M=2048, N=2048 (h*128+d), K=512.  128x128 CTA tile, 8x8 per thread.
// ---------------------------------------------------------------------------
__global__ __launch_bounds__(256) void knope_gemm(const float* __restrict__ kc,
                                                  const float* __restrict__ wkv) {
    __shared__ float sA[16][132];  // [k][m] transposed
    __shared__ float sB[16][132];  // [k][n]
    const int bx = blockIdx.x;     // head (n tile of 128)
    const int by = blockIdx.y;     // m tile of 128
    const int tid = threadIdx.x;
    const int tm = tid >> 4, tn = tid & 15;
    const int m0 = tm * 8, n0 = tn * 8;

    float acc[8][8];
#pragma unroll
    for (int i = 0; i < 8; i++)
#pragma unroll
        for (int j = 0; j < 8; j++) acc[i][j] = 0.f;

    for (int k0 = 0; k0 < DLORA; k0 += 16) {
        // A: 128 rows x 16 k  (512 float4), store transposed
#pragma unroll
        for (int t = 0; t < 2; t++) {
            int idx = tid + t * 256;
            int r = idx >> 2, c4 = idx & 3;
            float4 v = *(const float4*)(kc + (size_t)(by * 128 + r) * DLORA + k0 + c4 * 4);
            sA[c4 * 4 + 0][r] = v.x;
            sA[c4 * 4 + 1][r] = v.y;
            sA[c4 * 4 + 2][r] = v.z;
            sA[c4 * 4 + 3][r] = v.w;
        }
        // B: 16 k-rows x 128 cols (contiguous inside head block bx)
#pragma unroll
        for (int t = 0; t < 2; t++) {
            int idx = tid + t * 256;
            int r = idx >> 5, c4 = idx & 31;
            float4 v = *(const float4*)(wkv + (size_t)(k0 + r) * 4096 + bx * 256 + c4 * 4);
            *(float4*)(&sB[r][c4 * 4]) = v;
        }
        __syncthreads();
#pragma unroll
        for (int k = 0; k < 16; k++) {
            float4 a0 = *(float4*)&sA[k][m0];
            float4 a1 = *(float4*)&sA[k][m0 + 4];
            float4 b0 = *(float4*)&sB[k][n0];
            float4 b1 = *(float4*)&sB[k][n0 + 4];
            float av[8] = {a0.x, a0.y, a0.z, a0.w, a1.x, a1.y, a1.z, a1.w};
            float bv[8] = {b0.x, b0.y, b0.z, b0.w, b1.x, b1.y, b1.z, b1.w};
#pragma unroll
            for (int i = 0; i < 8; i++)
#pragma unroll
                for (int j = 0; j < 8; j++) acc[i][j] += av[i] * bv[j];
        }
        __syncthreads();
    }
#pragma unroll
    for (int i = 0; i < 8; i++) {
        float* dst = g_knope + (size_t)(by * 128 + m0 + i) * (NH * DNOPE) + bx * DNOPE + n0;
        *(float4*)dst = make_float4(acc[i][0], acc[i][1], acc[i][2], acc[i][3]);
        *(float4*)(dst + 4) = make_float4(acc[i][4], acc[i][5], acc[i][6], acc[i][7]);
    }
}

// ---------------------------------------------------------------------------
// Kernel 2: fused causal attention per (head, 64-row q tile).
//   pass 1: running rowmax / rowsum over key tiles (BN=32)
//   pass 2: P = exp(s-m)*inv_sum, latent O(64x512) += P @ Kc  (O in SMEM)
//   epilogue: out(64x128) = O @ w_uv[h]
// Thread map for S: 16 m-groups x 16 n-groups, 4m x 2n per thread.
// Thread map for PV/proj: 16 m-groups x 16 l/v-groups, 4 x 8 per thread.
// ---------------------------------------------------------------------------
__device__ __forceinline__ void compute_s(const float* __restrict__ sQ,
                                          const float* __restrict__ sK,
                                          int m0, int n0, int rq, int rk,
                                          float acc[4][2]) {
#pragma unroll
    for (int i = 0; i < 4; i++) { acc[i][0] = 0.f; acc[i][1] = 0.f; }
#pragma unroll 8
    for (int c4 = 0; c4 < 48; c4++) {
        int pq = ((c4 & ~7) | ((c4 ^ rq) & 7)) * 4;
        int pk = ((c4 & ~7) | ((c4 ^ rk) & 7)) * 4;
        float4 k0v = *(const float4*)(sK + (n0 + 0) * 192 + pk);
        float4 k1v = *(const float4*)(sK + (n0 + 1) * 192 + pk);
#pragma unroll
        for (int i = 0; i < 4; i++) {
            float4 qv = *(const float4*)(sQ + (m0 + i) * 192 + pq);
            acc[i][0] += qv.x * k0v.x + qv.y * k0v.y + qv.z * k0v.z + qv.w * k0v.w;
            acc[i][1] += qv.x * k1v.x + qv.y * k1v.y + qv.z * k1v.z + qv.w * k1v.w;
        }
    }
}

__global__ __launch_bounds__(256) void mla_attn(const float* __restrict__ q,
                                                const float* __restrict__ kc,
                                                const float* __restrict__ kpe,
                                                const float* __restrict__ wuv,
                                                float* __restrict__ out) {
    extern __shared__ float smem[];
    float* sQ = smem;                    // 64*192 = 12288 (swizzled)
    float* sK = sQ + 64 * 192;           // 32*192 = 6144 (reused as Kc/W chunk 32*132)
    float* sP = sK + 32 * 192;           // 64*36  = 2304
    float* sO = sP + 64 * 36;            // 64*516 = 33024

    const int qt = blockIdx.x, h = blockIdx.y;
    const int tid = threadIdx.x;
    const int tm = tid >> 4, tn = tid & 15;
    const int m0 = tm * 4, n0 = tn * 2;
    const int rq = tm, rk = tn >> 1;

    // load Q tile (swizzled), zero O accumulator
    for (int idx = tid; idx < 64 * 48; idx += 256) {
        int r = idx / 48, c4 = idx % 48;
        float4 v = *(const float4*)(q + (size_t)(qt * 64 + r) * (NH * DQK) + h * DQK + c4 * 4);
        int p = (c4 & ~7) | ((c4 ^ (r >> 2)) & 7);
        *(float4*)(sQ + r * 192 + p * 4) = v;
    }
    for (int idx = tid; idx < 64 * 516; idx += 256) sO[idx] = 0.f;
    __syncthreads();

    const int jmax = 2 * qt + 1;
    float m_run[4], s_run[4];
#pragma unroll
    for (int i = 0; i < 4; i++) { m_run[i] = -INFINITY; s_run[i] = 0.f; }

    // ---------------- PASS 1: softmax statistics ----------------
    for (int j = 0; j <= jmax; j++) {
        for (int idx = tid; idx < 32 * 48; idx += 256) {
            int r = idx / 48, c4 = idx % 48;
            int s = j * 32 + r;
            float4 v;
            if (c4 < 32) v = *(const float4*)(g_knope + (size_t)s * (NH * DNOPE) + h * DNOPE + c4 * 4);
            else         v = *(const float4*)(kpe + (size_t)s * DROPE + (c4 - 32) * 4);
            int p = (c4 & ~7) | ((c4 ^ (r >> 2)) & 7);
            *(float4*)(sK + r * 192 + p * 4) = v;
        }
        __syncthreads();

        float acc[4][2];
        compute_s(sQ, sK, m0, n0, rq, rk, acc);

#pragma unroll
        for (int i = 0; i < 4; i++) {
            int gm = qt * 64 + m0 + i;
            float s0 = (j * 32 + n0 + 0 <= gm) ? acc[i][0] * SCALE : -INFINITY;
            float s1 = (j * 32 + n0 + 1 <= gm) ? acc[i][1] * SCALE : -INFINITY;
            float tmax = fmaxf(s0, s1);
#pragma unroll
            for (int d = 1; d < 16; d <<= 1)
                tmax = fmaxf(tmax, __shfl_xor_sync(0xffffffffu, tmax, d));
            float mnew = fmaxf(m_run[i], tmax);        // finite for all rows from j=0
            float psum = __expf(s0 - mnew) + __expf(s1 - mnew);  // exp(-inf)=0 masks
#pragma unroll
            for (int d = 1; d < 16; d <<= 1)
                psum += __shfl_xor_sync(0xffffffffu, psum, d);
            float alpha = __expf(m_run[i] - mnew);
            s_run[i] = s_run[i] * alpha + psum;
            m_run[i] = mnew;
        }
        __syncthreads();
    }
    float inv[4];
#pragma unroll
    for (int i = 0; i < 4; i++) inv[i] = 1.f / s_run[i];

    // ---------------- PASS 2: P and latent accumulation ----------------
    const int lo = tn * 8;
    for (int j = 0; j <= jmax; j++) {
        for (int idx = tid; idx < 32 * 48; idx += 256) {
            int r = idx / 48, c4 = idx % 48;
            int s = j * 32 + r;
            float4 v;
            if (c4 < 32) v = *(const float4*)(g_knope + (size_t)s * (NH * DNOPE) + h * DNOPE + c4 * 4);
            else         v = *(const float4*)(kpe + (size_t)s * DROPE + (c4 - 32) * 4);
            int p = (c4 & ~7) | ((c4 ^ (r >> 2)) & 7);
            *(float4*)(sK + r * 192 + p * 4) = v;
        }
        __syncthreads();

        float acc[4][2];
        compute_s(sQ, sK, m0, n0, rq, rk, acc);

#pragma unroll
        for (int i = 0; i < 4; i++) {
            int gm = qt * 64 + m0 + i;
#pragma unroll
            for (int jj = 0; jj < 2; jj++) {
                int gn = j * 32 + n0 + jj;
                float s = (gn <= gm) ? acc[i][jj] * SCALE : -INFINITY;
                sP[(m0 + i) * 36 + n0 + jj] = __expf(s - m_run[i]) * inv[i];
            }
        }
        __syncthreads();   // P visible; sK free to be overwritten

#pragma unroll
        for (int lc = 0; lc < 4; lc++) {
            for (int idx = tid; idx < 1024; idx += 256) {
                int r = idx >> 5, c4 = idx & 31;
                *(float4*)(sK + r * 132 + c4 * 4) =
                    *(const float4*)(kc + (size_t)(j * 32 + r) * DLORA + lc * 128 + c4 * 4);
            }
            __syncthreads();

            float a[4][8];
#pragma unroll
            for (int i = 0; i < 4; i++)
#pragma unroll
                for (int v = 0; v < 8; v++) a[i][v] = 0.f;

#pragma unroll 4
            for (int n = 0; n < 32; n++) {
                float4 c0 = *(const float4*)(sK + n * 132 + lo);
                float4 c1 = *(const float4*)(sK + n * 132 + lo + 4);
                float cv[8] = {c0.x, c0.y, c0.z, c0.w, c1.x, c1.y, c1.z, c1.w};
#pragma unroll
                for (int i = 0; i < 4; i++) {
                    float p = sP[(m0 + i) * 36 + n];
#pragma unroll
                    for (int v = 0; v < 8; v++) a[i][v] += p * cv[v];
                }
            }
#pragma unroll
            for (int i = 0; i < 4; i++) {
                float* o = sO + (m0 + i) * 516 + lc * 128 + lo;
                float4 o0 = *(float4*)o, o1 = *(float4*)(o + 4);
                o0.x += a[i][0]; o0.y += a[i][1]; o0.z += a[i][2]; o0.w += a[i][3];
                o1.x += a[i][4]; o1.y += a[i][5]; o1.z += a[i][6]; o1.w += a[i][7];
                *(float4*)o = o0; *(float4*)(o + 4) = o1;
            }
            __syncthreads();
        }
    }

    // ---------------- epilogue: out = O @ w_uv[h] ----------------
    float a2[4][8];
#pragma unroll
    for (int i = 0; i < 4; i++)
#pragma unroll
        for (int v = 0; v < 8; v++) a2[i][v] = 0.f;

    for (int l0 = 0; l0 < DLORA; l0 += 32) {
        for (int idx = tid; idx < 1024; idx += 256) {
            int r = idx >> 5, c4 = idx & 31;
            *(float4*)(sK + r * 132 + c4 * 4) =
                *(const float4*)(wuv + (size_t)h * DLORA * DV + (size_t)(l0 + r) * DV + c4 * 4);
        }
        __syncthreads();
#pragma unroll 4
        for (int l = 0; l < 32; l++) {
            float4 w0 = *(const float4*)(sK + l * 132 + lo);
            float4 w1 = *(const float4*)(sK + l * 132 + lo + 4);
            float wv[8] = {w0.x, w0.y, w0.z, w0.w, w1.x, w1.y, w1.z, w1.w};
#pragma unroll
            for (int i = 0; i < 4; i++) {
                float ov = sO[(m0 + i) * 516 + l0 + l];
#pragma unroll
                for (int v = 0; v < 8; v++) a2[i][v] += ov * wv[v];
            }
        }
        __syncthreads();
    }
#pragma unroll
    for (int i = 0; i < 4; i++) {
        float* dst = out + (size_t)(qt * 64 + m0 + i) * (NH * DV) + h * DV + lo;
        *(float4*)dst = make_float4(a2[i][0], a2[i][1], a2[i][2], a2[i][3]);
        *(float4*)(dst + 4) = make_float4(a2[i][4], a2[i][5], a2[i][6], a2[i][7]);
    }
}

// ---------------------------------------------------------------------------
extern "C" void kernel_launch(void* const* d_in, const int* in_sizes, int n_in,
                              void* d_out, int out_size) {
    (void)in_sizes; (void)n_in; (void)out_size;
    const float* q   = (const float*)d_in[0];   // (T, H, 192)
    const float* kc  = (const float*)d_in[1];   // (T, 512)
    const float* kpe = (const float*)d_in[2];   // (T, 64)
    const float* wkv = (const float*)d_in[3];   // (512, 4096)
    const float* wuv = (const float*)d_in[4];   // (16, 512, 128)
    float* out = (float*)d_out;                 // (T, 2048)

    knope_gemm<<<dim3(16, 16), 256>>>(kc, wkv);

    const int smem_bytes = (64 * 192 + 32 * 192 + 64 * 36 + 64 * 516) * 4;  // 215040
    cudaFuncSetAttribute(mla_attn, cudaFuncAttributeMaxDynamicSharedMemorySize, smem_bytes);
    mla_attn<<<dim3(32, 16), 256, smem_bytes>>>(q, kc, kpe, wuv, out);
}

// round 5
// speedup vs baseline: 9.5541x; 9.5541x over previous
#include <cuda_runtime.h>
#include <cuda_fp16.h>
#include <math.h>
#include <stdint.h>

#define TSEQ   2048
#define NH     16
#define DLORA  512
#define SCALE  0.07216878364870323f

// ---------------- scratch (device globals; allocation-free) ----------------
__device__ __half g_kc_h[TSEQ * DLORA];          // [t][l]
__device__ __half g_kc_l[TSEQ * DLORA];
__device__ __half g_wt_h[4096 * DLORA];          // [n][l] combined weight^T
__device__ __half g_wt_l[4096 * DLORA];
__device__ __half g_ksp[TSEQ * NH * 384];        // [t][h][ hiN(128)|hiR(64)|loN(128)|loR(64) ]
__device__ __half g_vt_h[NH * 128 * TSEQ];       // [h][dv][t]
__device__ __half g_vt_l[NH * 128 * TSEQ];

// ---------------- helpers ----------------
__device__ __forceinline__ uint32_t smem_u32(const void* p) {
    uint32_t a;
    asm("{ .reg .u64 t; cvta.to.shared.u64 t, %1; cvt.u32.u64 %0, t; }" : "=r"(a) : "l"(p));
    return a;
}
__device__ __forceinline__ uint32_t pack2(float a, float b) {
    __half2 h = __floats2half2_rn(a, b);
    return *reinterpret_cast<uint32_t*>(&h);
}
__device__ __forceinline__ void ldsm4(uint32_t a, uint32_t& r0, uint32_t& r1, uint32_t& r2, uint32_t& r3) {
    asm volatile("ldmatrix.sync.aligned.m8n8.x4.shared.b16 {%0,%1,%2,%3}, [%4];"
                 : "=r"(r0), "=r"(r1), "=r"(r2), "=r"(r3) : "r"(a));
}
__device__ __forceinline__ void mma16816(float* c, uint32_t a0, uint32_t a1, uint32_t a2, uint32_t a3,
                                         uint32_t b0, uint32_t b1) {
    asm volatile("mma.sync.aligned.m16n8k16.row.col.f32.f16.f16.f32 "
                 "{%0,%1,%2,%3}, {%4,%5,%6,%7}, {%8,%9}, {%0,%1,%2,%3};"
                 : "+f"(c[0]), "+f"(c[1]), "+f"(c[2]), "+f"(c[3])
                 : "r"(a0), "r"(a1), "r"(a2), "r"(a3), "r"(b0), "r"(b1));
}
// address for a 16x16-half ldmatrix block at (row0, col0) in a [rows][pitch]-half tile
__device__ __forceinline__ uint32_t lmaddr(uint32_t base, int row0, int pitch, int col0, int lane) {
    return base + (uint32_t)(((row0 + (lane & 15)) * pitch + col0 + ((lane >> 4) << 3)) * 2);
}

// ---------------- converters ----------------
__global__ void conv_kc(const float* __restrict__ kc) {
    int i = blockIdx.x * blockDim.x + threadIdx.x;
    if (i >= TSEQ * DLORA) return;
    float x = kc[i];
    __half h = __float2half_rn(x);
    g_kc_h[i] = h;
    g_kc_l[i] = __float2half_rn(x - __half2float(h));
}
__global__ void conv_w(const float* __restrict__ wkv, const float* __restrict__ wuv) {
    int i = blockIdx.x * blockDim.x + threadIdx.x;
    if (i >= 4096 * DLORA) return;
    int n = i >> 9, l = i & 511;
    float x;
    if (n < 2048) x = wkv[(size_t)l * 4096 + ((n >> 7) << 8) + (n & 127)];
    else          x = wuv[(size_t)(((n - 2048) >> 7) * 512 + l) * 128 + ((n - 2048) & 127)];
    __half h = __float2half_rn(x);
    g_wt_h[i] = h;
    g_wt_l[i] = __float2half_rn(x - __half2float(h));
}
__global__ void conv_rope(const float* __restrict__ kpe) {
    int i = blockIdx.x * blockDim.x + threadIdx.x;
    if (i >= TSEQ * NH * 64) return;
    int t = i >> 10, h = (i >> 6) & 15, d = i & 63;
    float x = kpe[t * 64 + d];
    __half hi = __float2half_rn(x);
    g_ksp[(size_t)(t * 16 + h) * 384 + 128 + d] = hi;
    g_ksp[(size_t)(t * 16 + h) * 384 + 320 + d] = __float2half_rn(x - __half2float(hi));
}

// ---------------- pre-GEMM: D[t, n] = kc @ W^T (3 split terms, eff K=1536) ------
// grid (32 nt, 16 mt), 256 thr. nt<16: k_nope -> g_ksp; nt>=16: V -> g_vt (transposed)
#define PG_SMEM 69632
__global__ __launch_bounds__(256) void pregemm() {
    extern __shared__ __align__(16) char smraw[];
    __half* sA = (__half*)smraw;             // [128][136]
    __half* sB = sA + 128 * 136;             // [128][136]
    float*  sT = (float*)smraw;              // staging [128][129] (aliases sA/sB)
    const uint32_t sAb = smem_u32(sA), sBb = smem_u32(sB);
    const int nt = blockIdx.x, mt = blockIdx.y;
    const int tid = threadIdx.x, lane = tid & 31, w = tid >> 5;
    const int wm = w >> 2, wn = w & 3;       // warp tile: rows wm*64, cols wn*32
    const int g = lane >> 2, t2 = lane & 3;

    float acc[4][4][4];
#pragma unroll
    for (int a = 0; a < 4; a++)
#pragma unroll
        for (int b = 0; b < 4; b++)
#pragma unroll
            for (int c = 0; c < 4; c++) acc[a][b][c] = 0.f;

    for (int chunk = 0; chunk < 12; chunk++) {
        const int term = chunk >> 2, kk = (chunk & 3) * 128;
        const __half* Asrc = (term < 2) ? g_kc_h : g_kc_l;
        const __half* Bsrc = (term == 1) ? g_wt_l : g_wt_h;
        for (int idx = tid; idx < 128 * 16; idx += 256) {
            int r = idx >> 4, c = idx & 15;
            *(uint4*)(sA + r * 136 + c * 8) = *(const uint4*)(Asrc + (size_t)(mt * 128 + r) * 512 + kk + c * 8);
            *(uint4*)(sB + r * 136 + c * 8) = *(const uint4*)(Bsrc + (size_t)(nt * 128 + r) * 512 + kk + c * 8);
        }
        __syncthreads();
#pragma unroll
        for (int ks = 0; ks < 8; ks++) {
            uint32_t af[4][4];
#pragma unroll
            for (int mf = 0; mf < 4; mf++)
                ldsm4(lmaddr(sAb, wm * 64 + mf * 16, 136, ks * 16, lane),
                      af[mf][0], af[mf][1], af[mf][2], af[mf][3]);
#pragma unroll
            for (int ng = 0; ng < 2; ng++) {
                uint32_t b0, b1, b2, b3;
                ldsm4(lmaddr(sBb, wn * 32 + ng * 16, 136, ks * 16, lane), b0, b1, b2, b3);
#pragma unroll
                for (int mf = 0; mf < 4; mf++) {
                    mma16816(acc[mf][2 * ng],     af[mf][0], af[mf][1], af[mf][2], af[mf][3], b0, b2);
                    mma16816(acc[mf][2 * ng + 1], af[mf][0], af[mf][1], af[mf][2], af[mf][3], b1, b3);
                }
            }
        }
        __syncthreads();
    }

    // stage to sT [row][col] pitch 129
#pragma unroll
    for (int mf = 0; mf < 4; mf++)
#pragma unroll
        for (int nf = 0; nf < 4; nf++) {
            int rr = wm * 64 + mf * 16 + g, cc = wn * 32 + nf * 8 + 2 * t2;
            sT[rr * 129 + cc]       = acc[mf][nf][0];
            sT[rr * 129 + cc + 1]   = acc[mf][nf][1];
            sT[(rr + 8) * 129 + cc]     = acc[mf][nf][2];
            sT[(rr + 8) * 129 + cc + 1] = acc[mf][nf][3];
        }
    __syncthreads();

    if (tid < 128) {
        if (nt < 16) {  // k_nope row tid -> g_ksp hi/lo
            size_t base = (size_t)((mt * 128 + tid) * 16 + nt) * 384;
#pragma unroll
            for (int ch = 0; ch < 4; ch++) {
                uint32_t hh[16], ll[16];
#pragma unroll
                for (int i = 0; i < 16; i++) {
                    float f0 = sT[tid * 129 + ch * 32 + 2 * i];
                    float f1 = sT[tid * 129 + ch * 32 + 2 * i + 1];
                    __half h0 = __float2half_rn(f0), h1 = __float2half_rn(f1);
                    hh[i] = pack2(__half2float(h0), __half2float(h1));
                    ll[i] = pack2(f0 - __half2float(h0), f1 - __half2float(h1));
                }
#pragma unroll
                for (int k = 0; k < 4; k++) {
                    *(uint4*)(g_ksp + base + ch * 32 + k * 8) = make_uint4(hh[4*k], hh[4*k+1], hh[4*k+2], hh[4*k+3]);
                    *(uint4*)(g_ksp + base + 192 + ch * 32 + k * 8) = make_uint4(ll[4*k], ll[4*k+1], ll[4*k+2], ll[4*k+3]);
                }
            }
        } else {        // V column tid=dv -> g_vt rows (transpose)
            int h = nt - 16;
            size_t base = (size_t)(h * 128 + tid) * 2048 + mt * 128;
#pragma unroll
            for (int ch = 0; ch < 4; ch++) {
                uint32_t hh[16], ll[16];
#pragma unroll
                for (int i = 0; i < 16; i++) {
                    float f0 = sT[(ch * 32 + 2 * i) * 129 + tid];
                    float f1 = sT[(ch * 32 + 2 * i + 1) * 129 + tid];
                    __half h0 = __float2half_rn(f0), h1 = __float2half_rn(f1);
                    hh[i] = pack2(__half2float(h0), __half2float(h1));
                    ll[i] = pack2(f0 - __half2float(h0), f1 - __half2float(h1));
                }
#pragma unroll
                for (int k = 0; k < 4; k++) {
                    *(uint4*)(g_vt_h + base + ch * 32 + k * 8) = make_uint4(hh[4*k], hh[4*k+1], hh[4*k+2], hh[4*k+3]);
                    *(uint4*)(g_vt_l + base + ch * 32 + k * 8) = make_uint4(ll[4*k], ll[4*k+1], ll[4*k+2], ll[4*k+3]);
                }
            }
        }
    }
}

// ---------------- attention: grid (16 qt, 16 heads), 256 thr (8 warps x 16 rows) ---
#define AT_SMEM 221184
__global__ __launch_bounds__(256) void attn(const float* __restrict__ q, float* __restrict__ out) {
    extern __shared__ __align__(16) __half smh[];
    __half* sQ  = smh;                 // [128][200]  (192 used)
    __half* sK  = sQ + 128 * 200;      // [128][392]  (384 used: hi|lo)
    __half* sVh = sK + 128 * 392;      // [128][136]  rows=dv, cols=key
    __half* sVl = sVh + 128 * 136;
    const uint32_t sQb = smem_u32(sQ), sKb = smem_u32(sK);
    const uint32_t sVhb = smem_u32(sVh), sVlb = smem_u32(sVl);

    const int qt = 15 - blockIdx.x, h = blockIdx.y;
    const int tid = threadIdx.x, lane = tid & 31, w = tid >> 5;
    const int m0 = w * 16, g = lane >> 2, t2 = lane & 3;
    const int gr0 = qt * 128 + m0 + g, gr1 = gr0 + 8;

    // load+convert Q tile (hi only)
    for (int idx = tid; idx < 128 * 48; idx += 256) {
        int r = idx / 48, c = idx % 48;
        float4 v = *(const float4*)(q + (size_t)((qt * 128 + r) * 16 + h) * 192 + c * 4);
        uint32_t p0 = pack2(v.x, v.y), p1 = pack2(v.z, v.w);
        *(uint2*)(sQ + r * 200 + c * 4) = make_uint2(p0, p1);
    }

    float O[16][4];
#pragma unroll
    for (int f = 0; f < 16; f++)
#pragma unroll
        for (int c = 0; c < 4; c++) O[f][c] = 0.f;
    float mr0 = -INFINITY, mr1 = -INFINITY, sr0 = 0.f, sr1 = 0.f;

    for (int j = 0; j <= qt; j++) {
        // load K (hi|lo) and V hi/lo tiles
        for (int idx = tid; idx < 128 * 48; idx += 256) {
            int r = idx / 48, c = idx % 48;
            *(uint4*)(sK + r * 392 + c * 8) =
                *(const uint4*)(g_ksp + (size_t)((j * 128 + r) * 16 + h) * 384 + c * 8);
        }
        for (int idx = tid; idx < 128 * 16; idx += 256) {
            int r = idx >> 4, c = idx & 15;
            size_t src = (size_t)(h * 128 + r) * 2048 + j * 128 + c * 8;
            *(uint4*)(sVh + r * 136 + c * 8) = *(const uint4*)(g_vt_h + src);
            *(uint4*)(sVl + r * 136 + c * 8) = *(const uint4*)(g_vt_l + src);
        }
        __syncthreads();

        // S = Qhi @ (Khi + Klo)^T
        float Sc[16][4];
#pragma unroll
        for (int f = 0; f < 16; f++)
#pragma unroll
            for (int c = 0; c < 4; c++) Sc[f][c] = 0.f;
#pragma unroll
        for (int kk = 0; kk < 24; kk++) {
            int qk = (kk < 12) ? kk : kk - 12;
            uint32_t a0, a1, a2, a3;
            ldsm4(lmaddr(sQb, m0, 200, qk * 16, lane), a0, a1, a2, a3);
#pragma unroll
            for (int nf2 = 0; nf2 < 8; nf2++) {
                uint32_t b0, b1, b2, b3;
                ldsm4(lmaddr(sKb, nf2 * 16, 392, kk * 16, lane), b0, b1, b2, b3);
                mma16816(Sc[2 * nf2],     a0, a1, a2, a3, b0, b2);
                mma16816(Sc[2 * nf2 + 1], a0, a1, a2, a3, b1, b3);
            }
        }

        // mask + scale + online softmax
        float mx0 = -INFINITY, mx1 = -INFINITY;
#pragma unroll
        for (int f = 0; f < 16; f++) {
            int c0 = j * 128 + f * 8 + t2 * 2;
            float x0 = (c0     <= gr0) ? Sc[f][0] * SCALE : -INFINITY;
            float x1 = (c0 + 1 <= gr0) ? Sc[f][1] * SCALE : -INFINITY;
            float x2 = (c0     <= gr1) ? Sc[f][2] * SCALE : -INFINITY;
            float x3 = (c0 + 1 <= gr1) ? Sc[f][3] * SCALE : -INFINITY;
            Sc[f][0] = x0; Sc[f][1] = x1; Sc[f][2] = x2; Sc[f][3] = x3;
            mx0 = fmaxf(mx0, fmaxf(x0, x1));
            mx1 = fmaxf(mx1, fmaxf(x2, x3));
        }
        mx0 = fmaxf(mx0, __shfl_xor_sync(0xffffffffu, mx0, 1));
        mx0 = fmaxf(mx0, __shfl_xor_sync(0xffffffffu, mx0, 2));
        mx1 = fmaxf(mx1, __shfl_xor_sync(0xffffffffu, mx1, 1));
        mx1 = fmaxf(mx1, __shfl_xor_sync(0xffffffffu, mx1, 2));
        float mn0 = fmaxf(mr0, mx0), mn1 = fmaxf(mr1, mx1);
        float al0 = __expf(mr0 - mn0), al1 = __expf(mr1 - mn1);

        float rs0 = 0.f, rs1 = 0.f;
        uint32_t Pa[16], Pb[16];
#pragma unroll
        for (int f = 0; f < 16; f++) {
            float e0 = __expf(Sc[f][0] - mn0), e1 = __expf(Sc[f][1] - mn0);
            float e2 = __expf(Sc[f][2] - mn1), e3 = __expf(Sc[f][3] - mn1);
            rs0 += e0 + e1; rs1 += e2 + e3;
            Pa[f] = pack2(e0, e1); Pb[f] = pack2(e2, e3);
        }
        rs0 += __shfl_xor_sync(0xffffffffu, rs0, 1);
        rs0 += __shfl_xor_sync(0xffffffffu, rs0, 2);
        rs1 += __shfl_xor_sync(0xffffffffu, rs1, 1);
        rs1 += __shfl_xor_sync(0xffffffffu, rs1, 2);
        sr0 = sr0 * al0 + rs0; sr1 = sr1 * al1 + rs1;
        mr0 = mn0; mr1 = mn1;
#pragma unroll
        for (int f = 0; f < 16; f++) {
            O[f][0] *= al0; O[f][1] *= al0; O[f][2] *= al1; O[f][3] *= al1;
        }

        // O += P @ (Vhi + Vlo)
#pragma unroll
        for (int kc2 = 0; kc2 < 8; kc2++) {
            uint32_t a0 = Pa[2 * kc2], a1 = Pb[2 * kc2], a2 = Pa[2 * kc2 + 1], a3 = Pb[2 * kc2 + 1];
#pragma unroll
            for (int nf2 = 0; nf2 < 8; nf2++) {
                uint32_t b0, b1, b2, b3;
                ldsm4(lmaddr(sVhb, nf2 * 16, 136, kc2 * 16, lane), b0, b1, b2, b3);
                mma16816(O[2 * nf2],     a0, a1, a2, a3, b0, b2);
                mma16816(O[2 * nf2 + 1], a0, a1, a2, a3, b1, b3);
                ldsm4(lmaddr(sVlb, nf2 * 16, 136, kc2 * 16, lane), b0, b1, b2, b3);
                mma16816(O[2 * nf2],     a0, a1, a2, a3, b0, b2);
                mma16816(O[2 * nf2 + 1], a0, a1, a2, a3, b1, b3);
            }
        }
        __syncthreads();
    }

    // epilogue
    float inv0 = 1.f / sr0, inv1 = 1.f / sr1;
#pragma unroll
    for (int f = 0; f < 16; f++) {
        int col = h * 128 + f * 8 + t2 * 2;
        *(float2*)(out + (size_t)gr0 * 2048 + col) = make_float2(O[f][0] * inv0, O[f][1] * inv0);
        *(float2*)(out + (size_t)gr1 * 2048 + col) = make_float2(O[f][2] * inv1, O[f][3] * inv1);
    }
}

// ---------------------------------------------------------------------------
extern "C" void kernel_launch(void* const* d_in, const int* in_sizes, int n_in,
                              void* d_out, int out_size) {
    (void)in_sizes; (void)n_in; (void)out_size;
    const float* q   = (const float*)d_in[0];
    const float* kc  = (const float*)d_in[1];
    const float* kpe = (const float*)d_in[2];
    const float* wkv = (const float*)d_in[3];
    const float* wuv = (const float*)d_in[4];
    float* out = (float*)d_out;

    conv_kc  <<<(TSEQ * DLORA + 255) / 256, 256>>>(kc);
    conv_w   <<<(4096 * DLORA + 255) / 256, 256>>>(wkv, wuv);
    conv_rope<<<(TSEQ * NH * 64 + 255) / 256, 256>>>(kpe);

    cudaFuncSetAttribute(pregemm, cudaFuncAttributeMaxDynamicSharedMemorySize, PG_SMEM);
    cudaFuncSetAttribute(attn,    cudaFuncAttributeMaxDynamicSharedMemorySize, AT_SMEM);

    pregemm<<<dim3(32, 16), 256, PG_SMEM>>>();
    attn<<<dim3(16, 16), 256, AT_SMEM>>>(q, out);
}

// round 6
// speedup vs baseline: 15.1351x; 1.5841x over previous
#include <cuda_runtime.h>
#include <cuda_fp16.h>
#include <math.h>
#include <stdint.h>

#define TSEQ   2048
#define NH     16
#define DLORA  512
#define SCALE  0.07216878364870323f

// ---------------- scratch (device globals; allocation-free) ----------------
__device__ __half g_kc_h[TSEQ * DLORA];          // [t][l]
__device__ __half g_kc_l[TSEQ * DLORA];
__device__ __half g_wt_h[4096 * DLORA];          // [n][l] combined weight^T
__device__ __half g_wt_l[4096 * DLORA];
__device__ __half g_ksp[TSEQ * NH * 192];        // [t][h][ nope(128)|rope(64) ]  fp16
__device__ __half g_vt[NH * 128 * TSEQ];         // [h][dv][t]  fp16

// ---------------- helpers ----------------
__device__ __forceinline__ uint32_t smem_u32(const void* p) {
    uint32_t a;
    asm("{ .reg .u64 t; cvta.to.shared.u64 t, %1; cvt.u32.u64 %0, t; }" : "=r"(a) : "l"(p));
    return a;
}
__device__ __forceinline__ uint32_t pack2(float a, float b) {
    __half2 h = __floats2half2_rn(a, b);
    return *reinterpret_cast<uint32_t*>(&h);
}
__device__ __forceinline__ void ldsm4(uint32_t a, uint32_t& r0, uint32_t& r1, uint32_t& r2, uint32_t& r3) {
    asm volatile("ldmatrix.sync.aligned.m8n8.x4.shared.b16 {%0,%1,%2,%3}, [%4];"
                 : "=r"(r0), "=r"(r1), "=r"(r2), "=r"(r3) : "r"(a));
}
__device__ __forceinline__ void mma16816(float* c, uint32_t a0, uint32_t a1, uint32_t a2, uint32_t a3,
                                         uint32_t b0, uint32_t b1) {
    asm volatile("mma.sync.aligned.m16n8k16.row.col.f32.f16.f16.f32 "
                 "{%0,%1,%2,%3}, {%4,%5,%6,%7}, {%8,%9}, {%0,%1,%2,%3};"
                 : "+f"(c[0]), "+f"(c[1]), "+f"(c[2]), "+f"(c[3])
                 : "r"(a0), "r"(a1), "r"(a2), "r"(a3), "r"(b0), "r"(b1));
}
__device__ __forceinline__ uint32_t lmaddr(uint32_t base, int row0, int pitch, int col0, int lane) {
    return base + (uint32_t)(((row0 + (lane & 15)) * pitch + col0 + ((lane >> 4) << 3)) * 2);
}
__device__ __forceinline__ void cp16(uint32_t d, const void* s) {
    asm volatile("cp.async.cg.shared.global [%0], [%1], 16;" :: "r"(d), "l"(s));
}
#define CP_COMMIT() asm volatile("cp.async.commit_group;" ::: "memory")
#define CP_WAIT0()  asm volatile("cp.async.wait_group 0;" ::: "memory")

// ---------------- converters ----------------
__global__ void conv_kc(const float* __restrict__ kc) {
    int i = blockIdx.x * blockDim.x + threadIdx.x;
    if (i >= TSEQ * DLORA) return;
    float x = kc[i];
    __half h = __float2half_rn(x);
    g_kc_h[i] = h;
    g_kc_l[i] = __float2half_rn(x - __half2float(h));
}
__global__ void conv_w(const float* __restrict__ wkv, const float* __restrict__ wuv) {
    int i = blockIdx.x * blockDim.x + threadIdx.x;
    if (i >= 4096 * DLORA) return;
    int n = i >> 9, l = i & 511;
    float x;
    if (n < 2048) x = wkv[(size_t)l * 4096 + ((n >> 7) << 8) + (n & 127)];
    else          x = wuv[(size_t)(((n - 2048) >> 7) * 512 + l) * 128 + ((n - 2048) & 127)];
    __half h = __float2half_rn(x);
    g_wt_h[i] = h;
    g_wt_l[i] = __float2half_rn(x - __half2float(h));
}
__global__ void conv_rope(const float* __restrict__ kpe) {
    int i = blockIdx.x * blockDim.x + threadIdx.x;
    if (i >= TSEQ * NH * 64) return;
    int t = i >> 10, h = (i >> 6) & 15, d = i & 63;
    g_ksp[(size_t)(t * 16 + h) * 192 + 128 + d] = __float2half_rn(kpe[t * 64 + d]);
}

// ---------------- pre-GEMM: D[t, n] = kc @ W^T (3 split terms), cp.async 2-stage ---
// grid (32 nt, 16 mt), 256 thr. nt<16: k_nope -> g_ksp; nt>=16: V -> g_vt (transposed)
#define PG_SMEM 139264
__global__ __launch_bounds__(256) void pregemm() {
    extern __shared__ __align__(16) __half smh[];
    // buffers (halves): A0:0  B0:17408  A1:34816  B1:52224  (each 128x136)
    float* sT = (float*)smh;                 // staging [128][129] aliases A0+B0
    const uint32_t sb = smem_u32(smh);
    const int nt = blockIdx.x, mt = blockIdx.y;
    const int tid = threadIdx.x, lane = tid & 31, w = tid >> 5;
    const int wm = w >> 2, wn = w & 3;
    const int g = lane >> 2, t2 = lane & 3;

    float acc[4][4][4];
#pragma unroll
    for (int a = 0; a < 4; a++)
#pragma unroll
        for (int b = 0; b < 4; b++)
#pragma unroll
            for (int c = 0; c < 4; c++) acc[a][b][c] = 0.f;

    auto prefetch = [&](int chunk, int buf) {
        const int term = chunk >> 2, kk = (chunk & 3) * 128;
        const __half* Asrc = (term < 2) ? g_kc_h : g_kc_l;
        const __half* Bsrc = (term == 1) ? g_wt_l : g_wt_h;
        uint32_t ab = sb + (uint32_t)buf * 69632, bb = ab + 34816;
#pragma unroll
        for (int it = 0; it < 8; it++) {
            int idx = tid + it * 256;
            int r = idx >> 4, c = idx & 15;
            uint32_t off = (uint32_t)(r * 136 + c * 8) * 2;
            cp16(ab + off, Asrc + (size_t)(mt * 128 + r) * 512 + kk + c * 8);
            cp16(bb + off, Bsrc + (size_t)(nt * 128 + r) * 512 + kk + c * 8);
        }
    };

    prefetch(0, 0); CP_COMMIT();
    for (int chunk = 0; chunk < 12; chunk++) {
        CP_WAIT0();
        __syncthreads();
        if (chunk < 11) { prefetch(chunk + 1, (chunk + 1) & 1); CP_COMMIT(); }
        uint32_t ab = sb + (uint32_t)(chunk & 1) * 69632, bb = ab + 34816;
#pragma unroll
        for (int ks = 0; ks < 8; ks++) {
            uint32_t af[4][4];
#pragma unroll
            for (int mf = 0; mf < 4; mf++)
                ldsm4(lmaddr(ab, wm * 64 + mf * 16, 136, ks * 16, lane),
                      af[mf][0], af[mf][1], af[mf][2], af[mf][3]);
#pragma unroll
            for (int ng = 0; ng < 2; ng++) {
                uint32_t b0, b1, b2, b3;
                ldsm4(lmaddr(bb, wn * 32 + ng * 16, 136, ks * 16, lane), b0, b1, b2, b3);
#pragma unroll
                for (int mf = 0; mf < 4; mf++) {
                    mma16816(acc[mf][2 * ng],     af[mf][0], af[mf][1], af[mf][2], af[mf][3], b0, b2);
                    mma16816(acc[mf][2 * ng + 1], af[mf][0], af[mf][1], af[mf][2], af[mf][3], b1, b3);
                }
            }
        }
        __syncthreads();
    }

    // stage accumulators to sT [row][col] pitch 129
#pragma unroll
    for (int mf = 0; mf < 4; mf++)
#pragma unroll
        for (int nf = 0; nf < 4; nf++) {
            int rr = wm * 64 + mf * 16 + g, cc = wn * 32 + nf * 8 + 2 * t2;
            sT[rr * 129 + cc]       = acc[mf][nf][0];
            sT[rr * 129 + cc + 1]   = acc[mf][nf][1];
            sT[(rr + 8) * 129 + cc]     = acc[mf][nf][2];
            sT[(rr + 8) * 129 + cc + 1] = acc[mf][nf][3];
        }
    __syncthreads();

    if (tid < 128) {
        if (nt < 16) {  // k_nope row tid -> g_ksp (fp16 hi only)
            size_t base = (size_t)((mt * 128 + tid) * 16 + nt) * 192;
#pragma unroll
            for (int ch = 0; ch < 4; ch++) {
                uint32_t hh[16];
#pragma unroll
                for (int i = 0; i < 16; i++)
                    hh[i] = pack2(sT[tid * 129 + ch * 32 + 2 * i], sT[tid * 129 + ch * 32 + 2 * i + 1]);
#pragma unroll
                for (int k = 0; k < 4; k++)
                    *(uint4*)(g_ksp + base + ch * 32 + k * 8) = make_uint4(hh[4*k], hh[4*k+1], hh[4*k+2], hh[4*k+3]);
            }
        } else {        // V column tid=dv -> g_vt rows (transpose, fp16)
            int h = nt - 16;
            size_t base = (size_t)(h * 128 + tid) * 2048 + mt * 128;
#pragma unroll
            for (int ch = 0; ch < 4; ch++) {
                uint32_t hh[16];
#pragma unroll
                for (int i = 0; i < 16; i++)
                    hh[i] = pack2(sT[(ch * 32 + 2 * i) * 129 + tid], sT[(ch * 32 + 2 * i + 1) * 129 + tid]);
#pragma unroll
                for (int k = 0; k < 4; k++)
                    *(uint4*)(g_vt + base + ch * 32 + k * 8) = make_uint4(hh[4*k], hh[4*k+1], hh[4*k+2], hh[4*k+3]);
            }
        }
    }
}

// ---------------- attention: grid (16 qt, 16 heads), 256 thr, cp.async 2-stage ----
// smem halves: Q:0 (128x200) | K0:25600 | K1:51200 | V0:76800 (128x136) | V1:94208
#define AT_SMEM 223232
__global__ __launch_bounds__(256) void attn(const float* __restrict__ q, float* __restrict__ out) {
    extern __shared__ __align__(16) __half smh[];
    const uint32_t sb = smem_u32(smh);
    const uint32_t sQb = sb;
    const int qt = 15 - blockIdx.x, h = blockIdx.y;
    const int tid = threadIdx.x, lane = tid & 31, w = tid >> 5;
    const int m0 = w * 16, g = lane >> 2, t2 = lane & 3;
    const int gr0 = qt * 128 + m0 + g, gr1 = gr0 + 8;

    // stage Q (fp16 hi)
    for (int idx = tid; idx < 128 * 48; idx += 256) {
        int r = idx / 48, c = idx % 48;
        float4 v = *(const float4*)(q + (size_t)((qt * 128 + r) * 16 + h) * 192 + c * 4);
        *(uint2*)(smh + r * 200 + c * 4) = make_uint2(pack2(v.x, v.y), pack2(v.z, v.w));
    }

    auto prefetch = [&](int j, int buf) {
        uint32_t kb = sb + (25600u + (uint32_t)buf * 25600u) * 2;
        uint32_t vb = sb + (76800u + (uint32_t)buf * 17408u) * 2;
#pragma unroll
        for (int it = 0; it < 12; it++) {
            int idx = tid + it * 256;
            int r = idx / 24, c = idx % 24;
            cp16(kb + (uint32_t)(r * 200 + c * 8) * 2,
                 g_ksp + (size_t)((j * 128 + r) * 16 + h) * 192 + c * 8);
        }
#pragma unroll
        for (int it = 0; it < 8; it++) {
            int idx = tid + it * 256;
            int r = idx >> 4, c = idx & 15;
            cp16(vb + (uint32_t)(r * 136 + c * 8) * 2,
                 g_vt + (size_t)(h * 128 + r) * 2048 + j * 128 + c * 8);
        }
    };

    prefetch(0, 0); CP_COMMIT();

    float O[16][4];
#pragma unroll
    for (int f = 0; f < 16; f++)
#pragma unroll
        for (int c = 0; c < 4; c++) O[f][c] = 0.f;
    float mr0 = -INFINITY, mr1 = -INFINITY, sr0 = 0.f, sr1 = 0.f;

    for (int j = 0; j <= qt; j++) {
        CP_WAIT0();
        __syncthreads();
        if (j < qt) { prefetch(j + 1, (j + 1) & 1); CP_COMMIT(); }
        const uint32_t sKb = sb + (25600u + (uint32_t)(j & 1) * 25600u) * 2;
        const uint32_t sVb = sb + (76800u + (uint32_t)(j & 1) * 17408u) * 2;

        // S = Qhi @ Khi^T   (12 k-steps of 16)
        float Sc[16][4];
#pragma unroll
        for (int f = 0; f < 16; f++)
#pragma unroll
            for (int c = 0; c < 4; c++) Sc[f][c] = 0.f;
#pragma unroll
        for (int kk = 0; kk < 12; kk++) {
            uint32_t a0, a1, a2, a3;
            ldsm4(lmaddr(sQb, m0, 200, kk * 16, lane), a0, a1, a2, a3);
#pragma unroll
            for (int nf2 = 0; nf2 < 8; nf2++) {
                uint32_t b0, b1, b2, b3;
                ldsm4(lmaddr(sKb, nf2 * 16, 200, kk * 16, lane), b0, b1, b2, b3);
                mma16816(Sc[2 * nf2],     a0, a1, a2, a3, b0, b2);
                mma16816(Sc[2 * nf2 + 1], a0, a1, a2, a3, b1, b3);
            }
        }

        // mask + scale + online softmax
        float mx0 = -INFINITY, mx1 = -INFINITY;
#pragma unroll
        for (int f = 0; f < 16; f++) {
            int c0 = j * 128 + f * 8 + t2 * 2;
            float x0 = (c0     <= gr0) ? Sc[f][0] * SCALE : -INFINITY;
            float x1 = (c0 + 1 <= gr0) ? Sc[f][1] * SCALE : -INFINITY;
            float x2 = (c0     <= gr1) ? Sc[f][2] * SCALE : -INFINITY;
            float x3 = (c0 + 1 <= gr1) ? Sc[f][3] * SCALE : -INFINITY;
            Sc[f][0] = x0; Sc[f][1] = x1; Sc[f][2] = x2; Sc[f][3] = x3;
            mx0 = fmaxf(mx0, fmaxf(x0, x1));
            mx1 = fmaxf(mx1, fmaxf(x2, x3));
        }
        mx0 = fmaxf(mx0, __shfl_xor_sync(0xffffffffu, mx0, 1));
        mx0 = fmaxf(mx0, __shfl_xor_sync(0xffffffffu, mx0, 2));
        mx1 = fmaxf(mx1, __shfl_xor_sync(0xffffffffu, mx1, 1));
        mx1 = fmaxf(mx1, __shfl_xor_sync(0xffffffffu, mx1, 2));
        float mn0 = fmaxf(mr0, mx0), mn1 = fmaxf(mr1, mx1);
        float al0 = __expf(mr0 - mn0), al1 = __expf(mr1 - mn1);

        float rs0 = 0.f, rs1 = 0.f;
        uint32_t Pa[16], Pb[16];
#pragma unroll
        for (int f = 0; f < 16; f++) {
            float e0 = __expf(Sc[f][0] - mn0), e1 = __expf(Sc[f][1] - mn0);
            float e2 = __expf(Sc[f][2] - mn1), e3 = __expf(Sc[f][3] - mn1);
            rs0 += e0 + e1; rs1 += e2 + e3;
            Pa[f] = pack2(e0, e1); Pb[f] = pack2(e2, e3);
        }
        rs0 += __shfl_xor_sync(0xffffffffu, rs0, 1);
        rs0 += __shfl_xor_sync(0xffffffffu, rs0, 2);
        rs1 += __shfl_xor_sync(0xffffffffu, rs1, 1);
        rs1 += __shfl_xor_sync(0xffffffffu, rs1, 2);
        sr0 = sr0 * al0 + rs0; sr1 = sr1 * al1 + rs1;
        mr0 = mn0; mr1 = mn1;
#pragma unroll
        for (int f = 0; f < 16; f++) {
            O[f][0] *= al0; O[f][1] *= al0; O[f][2] *= al1; O[f][3] *= al1;
        }

        // O += P @ V   (8 k-steps of 16)
#pragma unroll
        for (int kc2 = 0; kc2 < 8; kc2++) {
            uint32_t a0 = Pa[2 * kc2], a1 = Pb[2 * kc2], a2 = Pa[2 * kc2 + 1], a3 = Pb[2 * kc2 + 1];
#pragma unroll
            for (int nf2 = 0; nf2 < 8; nf2++) {
                uint32_t b0, b1, b2, b3;
                ldsm4(lmaddr(sVb, nf2 * 16, 136, kc2 * 16, lane), b0, b1, b2, b3);
                mma16816(O[2 * nf2],     a0, a1, a2, a3, b0, b2);
                mma16816(O[2 * nf2 + 1], a0, a1, a2, a3, b1, b3);
            }
        }
        __syncthreads();
    }

    // epilogue
    float inv0 = 1.f / sr0, inv1 = 1.f / sr1;
#pragma unroll
    for (int f = 0; f < 16; f++) {
        int col = h * 128 + f * 8 + t2 * 2;
        *(float2*)(out + (size_t)gr0 * 2048 + col) = make_float2(O[f][0] * inv0, O[f][1] * inv0);
        *(float2*)(out + (size_t)gr1 * 2048 + col) = make_float2(O[f][2] * inv1, O[f][3] * inv1);
    }
}

// ---------------------------------------------------------------------------
extern "C" void kernel_launch(void* const* d_in, const int* in_sizes, int n_in,
                              void* d_out, int out_size) {
    (void)in_sizes; (void)n_in; (void)out_size;
    const float* q   = (const float*)d_in[0];
    const float* kc  = (const float*)d_in[1];
    const float* kpe = (const float*)d_in[2];
    const float* wkv = (const float*)d_in[3];
    const float* wuv = (const float*)d_in[4];
    float* out = (float*)d_out;

    conv_kc  <<<(TSEQ * DLORA + 255) / 256, 256>>>(kc);
    conv_w   <<<(4096 * DLORA + 255) / 256, 256>>>(wkv, wuv);
    conv_rope<<<(TSEQ * NH * 64 + 255) / 256, 256>>>(kpe);

    cudaFuncSetAttribute(pregemm, cudaFuncAttributeMaxDynamicSharedMemorySize, PG_SMEM);
    cudaFuncSetAttribute(attn,    cudaFuncAttributeMaxDynamicSharedMemorySize, AT_SMEM);

    pregemm<<<dim3(32, 16), 256, PG_SMEM>>>();
    attn<<<dim3(16, 16), 256, AT_SMEM>>>(q, out);
}

// round 7
// speedup vs baseline: 17.1399x; 1.1325x over previous
#include <cuda_runtime.h>
#include <cuda_fp16.h>
#include <math.h>
#include <stdint.h>

#define TSEQ   2048
#define NH     16
#define DLORA  512
// SCALE * log2(e)
#define QS     0.1041277131f

// ---------------- scratch (device globals; allocation-free) ----------------
__device__ __half g_kc_h[TSEQ * DLORA];          // [t][l]
__device__ __half g_kc_l[TSEQ * DLORA];
__device__ __half g_wt_h[4096 * DLORA];          // [n][l] combined weight^T (hi only)
__device__ __half g_ksp[TSEQ * NH * 192];        // [t][h][ nope(128)|rope(64) ]  fp16
__device__ __half g_vt[NH * 128 * TSEQ];         // [h][dv][t]  fp16

// ---------------- helpers ----------------
__device__ __forceinline__ uint32_t smem_u32(const void* p) {
    uint32_t a;
    asm("{ .reg .u64 t; cvta.to.shared.u64 t, %1; cvt.u32.u64 %0, t; }" : "=r"(a) : "l"(p));
    return a;
}
__device__ __forceinline__ uint32_t pack2(float a, float b) {
    __half2 h = __floats2half2_rn(a, b);
    return *reinterpret_cast<uint32_t*>(&h);
}
__device__ __forceinline__ void ldsm4(uint32_t a, uint32_t& r0, uint32_t& r1, uint32_t& r2, uint32_t& r3) {
    asm volatile("ldmatrix.sync.aligned.m8n8.x4.shared.b16 {%0,%1,%2,%3}, [%4];"
                 : "=r"(r0), "=r"(r1), "=r"(r2), "=r"(r3) : "r"(a));
}
__device__ __forceinline__ void mma16816(float* c, uint32_t a0, uint32_t a1, uint32_t a2, uint32_t a3,
                                         uint32_t b0, uint32_t b1) {
    asm volatile("mma.sync.aligned.m16n8k16.row.col.f32.f16.f16.f32 "
                 "{%0,%1,%2,%3}, {%4,%5,%6,%7}, {%8,%9}, {%0,%1,%2,%3};"
                 : "+f"(c[0]), "+f"(c[1]), "+f"(c[2]), "+f"(c[3])
                 : "r"(a0), "r"(a1), "r"(a2), "r"(a3), "r"(b0), "r"(b1));
}
__device__ __forceinline__ uint32_t lmaddr(uint32_t base, int row0, int pitch, int col0, int lane) {
    return base + (uint32_t)(((row0 + (lane & 15)) * pitch + col0 + ((lane >> 4) << 3)) * 2);
}
__device__ __forceinline__ void cp16(uint32_t d, const void* s) {
    asm volatile("cp.async.cg.shared.global [%0], [%1], 16;" :: "r"(d), "l"(s));
}
#define CP_COMMIT() asm volatile("cp.async.commit_group;" ::: "memory")
#define CP_WAIT0()  asm volatile("cp.async.wait_group 0;" ::: "memory")

// ---------------- converters ----------------
__global__ void conv_kc(const float* __restrict__ kc) {
    int i = blockIdx.x * blockDim.x + threadIdx.x;
    if (i >= TSEQ * DLORA) return;
    float x = kc[i];
    __half h = __float2half_rn(x);
    g_kc_h[i] = h;
    g_kc_l[i] = __float2half_rn(x - __half2float(h));
}
__global__ void conv_w(const float* __restrict__ wkv, const float* __restrict__ wuv) {
    int i = blockIdx.x * blockDim.x + threadIdx.x;
    if (i >= 4096 * DLORA) return;
    int n = i >> 9, l = i & 511;
    float x;
    if (n < 2048) x = wkv[(size_t)l * 4096 + ((n >> 7) << 8) + (n & 127)];
    else          x = wuv[(size_t)(((n - 2048) >> 7) * 512 + l) * 128 + ((n - 2048) & 127)];
    g_wt_h[i] = __float2half_rn(x);
}
__global__ void conv_rope(const float* __restrict__ kpe) {
    int i = blockIdx.x * blockDim.x + threadIdx.x;
    if (i >= TSEQ * NH * 64) return;
    int t = i >> 10, h = (i >> 6) & 15, d = i & 63;
    g_ksp[(size_t)(t * 16 + h) * 192 + 128 + d] = __float2half_rn(kpe[t * 64 + d]);
}

// ---------------- pre-GEMM: D = (kc_hi + kc_lo) @ W_hi^T, single-stage, 2 CTA/SM --
// smem halves: Ah:0  Al:17408  B:34816  (each 128x136); sT float staging aliases.
#define PG_SMEM 104448
__global__ __launch_bounds__(256, 2) void pregemm() {
    extern __shared__ __align__(16) __half smh[];
    float* sT = (float*)smh;
    const uint32_t sb = smem_u32(smh);
    const uint32_t Ahb = sb, Alb = sb + 17408u * 2, Bb = sb + 34816u * 2;
    const int nt = blockIdx.x, mt = blockIdx.y;
    const int tid = threadIdx.x, lane = tid & 31, w = tid >> 5;
    const int wm = w >> 2, wn = w & 3;
    const int g = lane >> 2, t2 = lane & 3;

    float acc[4][4][4];
#pragma unroll
    for (int a = 0; a < 4; a++)
#pragma unroll
        for (int b = 0; b < 4; b++)
#pragma unroll
            for (int c = 0; c < 4; c++) acc[a][b][c] = 0.f;

    for (int chunk = 0; chunk < 4; chunk++) {
        const int kk = chunk * 128;
#pragma unroll
        for (int it = 0; it < 8; it++) {
            int idx = tid + it * 256;
            int r = idx >> 4, c = idx & 15;
            uint32_t off = (uint32_t)(r * 136 + c * 8) * 2;
            cp16(Ahb + off, g_kc_h + (size_t)(mt * 128 + r) * 512 + kk + c * 8);
            cp16(Alb + off, g_kc_l + (size_t)(mt * 128 + r) * 512 + kk + c * 8);
            cp16(Bb  + off, g_wt_h + (size_t)(nt * 128 + r) * 512 + kk + c * 8);
        }
        CP_COMMIT();
        CP_WAIT0();
        __syncthreads();
#pragma unroll
        for (int half = 0; half < 2; half++) {
            uint32_t ab = half ? Alb : Ahb;
#pragma unroll
            for (int ks = 0; ks < 8; ks++) {
                uint32_t af[4][4];
#pragma unroll
                for (int mf = 0; mf < 4; mf++)
                    ldsm4(lmaddr(ab, wm * 64 + mf * 16, 136, ks * 16, lane),
                          af[mf][0], af[mf][1], af[mf][2], af[mf][3]);
#pragma unroll
                for (int ng = 0; ng < 2; ng++) {
                    uint32_t b0, b1, b2, b3;
                    ldsm4(lmaddr(Bb, wn * 32 + ng * 16, 136, ks * 16, lane), b0, b1, b2, b3);
#pragma unroll
                    for (int mf = 0; mf < 4; mf++) {
                        mma16816(acc[mf][2 * ng],     af[mf][0], af[mf][1], af[mf][2], af[mf][3], b0, b2);
                        mma16816(acc[mf][2 * ng + 1], af[mf][0], af[mf][1], af[mf][2], af[mf][3], b1, b3);
                    }
                }
            }
        }
        __syncthreads();
    }

    // stage accumulators to sT [row][col] pitch 129
#pragma unroll
    for (int mf = 0; mf < 4; mf++)
#pragma unroll
        for (int nf = 0; nf < 4; nf++) {
            int rr = wm * 64 + mf * 16 + g, cc = wn * 32 + nf * 8 + 2 * t2;
            sT[rr * 129 + cc]       = acc[mf][nf][0];
            sT[rr * 129 + cc + 1]   = acc[mf][nf][1];
            sT[(rr + 8) * 129 + cc]     = acc[mf][nf][2];
            sT[(rr + 8) * 129 + cc + 1] = acc[mf][nf][3];
        }
    __syncthreads();

    if (tid < 128) {
        if (nt < 16) {  // k_nope row tid -> g_ksp (fp16)
            size_t base = (size_t)((mt * 128 + tid) * 16 + nt) * 192;
#pragma unroll
            for (int ch = 0; ch < 4; ch++) {
                uint32_t hh[16];
#pragma unroll
                for (int i = 0; i < 16; i++)
                    hh[i] = pack2(sT[tid * 129 + ch * 32 + 2 * i], sT[tid * 129 + ch * 32 + 2 * i + 1]);
#pragma unroll
                for (int k = 0; k < 4; k++)
                    *(uint4*)(g_ksp + base + ch * 32 + k * 8) = make_uint4(hh[4*k], hh[4*k+1], hh[4*k+2], hh[4*k+3]);
            }
        } else {        // V column tid=dv -> g_vt rows (transpose, fp16)
            int h = nt - 16;
            size_t base = (size_t)(h * 128 + tid) * 2048 + mt * 128;
#pragma unroll
            for (int ch = 0; ch < 4; ch++) {
                uint32_t hh[16];
#pragma unroll
                for (int i = 0; i < 16; i++)
                    hh[i] = pack2(sT[(ch * 32 + 2 * i) * 129 + tid], sT[(ch * 32 + 2 * i + 1) * 129 + tid]);
#pragma unroll
                for (int k = 0; k < 4; k++)
                    *(uint4*)(g_vt + base + ch * 32 + k * 8) = make_uint4(hh[4*k], hh[4*k+1], hh[4*k+2], hh[4*k+3]);
            }
        }
    }
}

// ---------------- attention: 64-row q-tiles, 128 thr, single-stage, 2 CTA/SM ------
// smem halves: Q:0 (64x200) | K:12800 (128x200) | V:38400 (128x136)   = 111616 B
#define AT_SMEM 111616
__global__ __launch_bounds__(128, 2) void attn(const float* __restrict__ q, float* __restrict__ out) {
    extern __shared__ __align__(16) __half smh[];
    const uint32_t sb = smem_u32(smh);
    const uint32_t sQb = sb, sKb = sb + 12800u * 2, sVb = sb + 38400u * 2;
    const int qt = 31 - blockIdx.x, h = blockIdx.y;   // 64-row q tile index
    const int tid = threadIdx.x, lane = tid & 31, w = tid >> 5;
    const int m0 = w * 16, g = lane >> 2, t2 = lane & 3;
    const int gr0 = qt * 64 + m0 + g, gr1 = gr0 + 8;
    const int jmax = (qt * 64 + 63) >> 7;

    // stage Q (fp16, prescaled by SCALE*log2e)
    for (int idx = tid; idx < 64 * 48; idx += 128) {
        int r = idx / 48, c = idx % 48;
        float4 v = *(const float4*)(q + (size_t)((qt * 64 + r) * 16 + h) * 192 + c * 4);
        *(uint2*)(smh + r * 200 + c * 4) =
            make_uint2(pack2(v.x * QS, v.y * QS), pack2(v.z * QS, v.w * QS));
    }

    float O[16][4];
#pragma unroll
    for (int f = 0; f < 16; f++)
#pragma unroll
        for (int c = 0; c < 4; c++) O[f][c] = 0.f;
    float mr0 = -INFINITY, mr1 = -INFINITY, sr0 = 0.f, sr1 = 0.f;

    for (int j = 0; j <= jmax; j++) {
        // load K, V tiles (single stage)
#pragma unroll
        for (int it = 0; it < 24; it++) {
            int idx = tid + it * 128;
            int r = idx / 24, c = idx % 24;
            cp16(sKb + (uint32_t)(r * 200 + c * 8) * 2,
                 g_ksp + (size_t)((j * 128 + r) * 16 + h) * 192 + c * 8);
        }
#pragma unroll
        for (int it = 0; it < 16; it++) {
            int idx = tid + it * 128;
            int r = idx >> 4, c = idx & 15;
            cp16(sVb + (uint32_t)(r * 136 + c * 8) * 2,
                 g_vt + (size_t)(h * 128 + r) * 2048 + j * 128 + c * 8);
        }
        CP_COMMIT();
        CP_WAIT0();
        __syncthreads();

        // S = Q @ K^T (already includes SCALE*log2e)
        float Sc[16][4];
#pragma unroll
        for (int f = 0; f < 16; f++)
#pragma unroll
            for (int c = 0; c < 4; c++) Sc[f][c] = 0.f;
#pragma unroll
        for (int kk = 0; kk < 12; kk++) {
            uint32_t a0, a1, a2, a3;
            ldsm4(lmaddr(sQb, m0, 200, kk * 16, lane), a0, a1, a2, a3);
#pragma unroll
            for (int nf2 = 0; nf2 < 8; nf2++) {
                uint32_t b0, b1, b2, b3;
                ldsm4(lmaddr(sKb, nf2 * 16, 200, kk * 16, lane), b0, b1, b2, b3);
                mma16816(Sc[2 * nf2],     a0, a1, a2, a3, b0, b2);
                mma16816(Sc[2 * nf2 + 1], a0, a1, a2, a3, b1, b3);
            }
        }

        // mask + online softmax (base-2)
        float mx0 = -INFINITY, mx1 = -INFINITY;
#pragma unroll
        for (int f = 0; f < 16; f++) {
            int c0 = j * 128 + f * 8 + t2 * 2;
            float x0 = (c0     <= gr0) ? Sc[f][0] : -INFINITY;
            float x1 = (c0 + 1 <= gr0) ? Sc[f][1] : -INFINITY;
            float x2 = (c0     <= gr1) ? Sc[f][2] : -INFINITY;
            float x3 = (c0 + 1 <= gr1) ? Sc[f][3] : -INFINITY;
            Sc[f][0] = x0; Sc[f][1] = x1; Sc[f][2] = x2; Sc[f][3] = x3;
            mx0 = fmaxf(mx0, fmaxf(x0, x1));
            mx1 = fmaxf(mx1, fmaxf(x2, x3));
        }
        mx0 = fmaxf(mx0, __shfl_xor_sync(0xffffffffu, mx0, 1));
        mx0 = fmaxf(mx0, __shfl_xor_sync(0xffffffffu, mx0, 2));
        mx1 = fmaxf(mx1, __shfl_xor_sync(0xffffffffu, mx1, 1));
        mx1 = fmaxf(mx1, __shfl_xor_sync(0xffffffffu, mx1, 2));
        float mn0 = fmaxf(mr0, mx0), mn1 = fmaxf(mr1, mx1);
        float al0 = exp2f(mr0 - mn0), al1 = exp2f(mr1 - mn1);

        float rs0 = 0.f, rs1 = 0.f;
        uint32_t Pa[16], Pb[16];
#pragma unroll
        for (int f = 0; f < 16; f++) {
            float e0 = exp2f(Sc[f][0] - mn0), e1 = exp2f(Sc[f][1] - mn0);
            float e2 = exp2f(Sc[f][2] - mn1), e3 = exp2f(Sc[f][3] - mn1);
            rs0 += e0 + e1; rs1 += e2 + e3;
            Pa[f] = pack2(e0, e1); Pb[f] = pack2(e2, e3);
        }
        rs0 += __shfl_xor_sync(0xffffffffu, rs0, 1);
        rs0 += __shfl_xor_sync(0xffffffffu, rs0, 2);
        rs1 += __shfl_xor_sync(0xffffffffu, rs1, 1);
        rs1 += __shfl_xor_sync(0xffffffffu, rs1, 2);
        sr0 = sr0 * al0 + rs0; sr1 = sr1 * al1 + rs1;
        mr0 = mn0; mr1 = mn1;
#pragma unroll
        for (int f = 0; f < 16; f++) {
            O[f][0] *= al0; O[f][1] *= al0; O[f][2] *= al1; O[f][3] *= al1;
        }

        // O += P @ V
#pragma unroll
        for (int kc2 = 0; kc2 < 8; kc2++) {
            uint32_t a0 = Pa[2 * kc2], a1 = Pb[2 * kc2], a2 = Pa[2 * kc2 + 1], a3 = Pb[2 * kc2 + 1];
#pragma unroll
            for (int nf2 = 0; nf2 < 8; nf2++) {
                uint32_t b0, b1, b2, b3;
                ldsm4(lmaddr(sVb, nf2 * 16, 136, kc2 * 16, lane), b0, b1, b2, b3);
                mma16816(O[2 * nf2],     a0, a1, a2, a3, b0, b2);
                mma16816(O[2 * nf2 + 1], a0, a1, a2, a3, b1, b3);
            }
        }
        __syncthreads();
    }

    // epilogue
    float inv0 = 1.f / sr0, inv1 = 1.f / sr1;
#pragma unroll
    for (int f = 0; f < 16; f++) {
        int col = h * 128 + f * 8 + t2 * 2;
        *(float2*)(out + (size_t)gr0 * 2048 + col) = make_float2(O[f][0] * inv0, O[f][1] * inv0);
        *(float2*)(out + (size_t)gr1 * 2048 + col) = make_float2(O[f][2] * inv1, O[f][3] * inv1);
    }
}

// ---------------------------------------------------------------------------
extern "C" void kernel_launch(void* const* d_in, const int* in_sizes, int n_in,
                              void* d_out, int out_size) {
    (void)in_sizes; (void)n_in; (void)out_size;
    const float* q   = (const float*)d_in[0];
    const float* kc  = (const float*)d_in[1];
    const float* kpe = (const float*)d_in[2];
    const float* wkv = (const float*)d_in[3];
    const float* wuv = (const float*)d_in[4];
    float* out = (float*)d_out;

    conv_kc  <<<(TSEQ * DLORA + 255) / 256, 256>>>(kc);
    conv_w   <<<(4096 * DLORA + 255) / 256, 256>>>(wkv, wuv);
    conv_rope<<<(TSEQ * NH * 64 + 255) / 256, 256>>>(kpe);

    cudaFuncSetAttribute(pregemm, cudaFuncAttributeMaxDynamicSharedMemorySize, PG_SMEM);
    cudaFuncSetAttribute(attn,    cudaFuncAttributeMaxDynamicSharedMemorySize, AT_SMEM);

    pregemm<<<dim3(32, 16), 256, PG_SMEM>>>();
    attn<<<dim3(32, 16), 128, AT_SMEM>>>(q, out);
}

// round 8
// speedup vs baseline: 23.2320x; 1.3554x over previous
#include <cuda_runtime.h>
#include <cuda_fp16.h>
#include <math.h>
#include <stdint.h>

#define TSEQ   2048
#define NH     16
#define DLORA  512
// SCALE * log2(e)
#define QS     0.1041277131f

// ---------------- scratch (device globals; allocation-free) ----------------
__device__ __half g_kc_h[TSEQ * DLORA];          // [t][l]
__device__ __half g_wt_h[4096 * DLORA];          // [n][l] combined weight^T (hi only)
__device__ __half g_ksp[TSEQ * NH * 192];        // [t][h][ nope(128)|rope(64) ]  fp16
__device__ __half g_vt[NH * 128 * TSEQ];         // [h][dv][t]  fp16

// ---------------- helpers ----------------
__device__ __forceinline__ uint32_t smem_u32(const void* p) {
    uint32_t a;
    asm("{ .reg .u64 t; cvta.to.shared.u64 t, %1; cvt.u32.u64 %0, t; }" : "=r"(a) : "l"(p));
    return a;
}
__device__ __forceinline__ uint32_t pack2(float a, float b) {
    __half2 h = __floats2half2_rn(a, b);
    return *reinterpret_cast<uint32_t*>(&h);
}
__device__ __forceinline__ void ldsm4(uint32_t a, uint32_t& r0, uint32_t& r1, uint32_t& r2, uint32_t& r3) {
    asm volatile("ldmatrix.sync.aligned.m8n8.x4.shared.b16 {%0,%1,%2,%3}, [%4];"
                 : "=r"(r0), "=r"(r1), "=r"(r2), "=r"(r3) : "r"(a));
}
__device__ __forceinline__ void mma16816(float* c, uint32_t a0, uint32_t a1, uint32_t a2, uint32_t a3,
                                         uint32_t b0, uint32_t b1) {
    asm volatile("mma.sync.aligned.m16n8k16.row.col.f32.f16.f16.f32 "
                 "{%0,%1,%2,%3}, {%4,%5,%6,%7}, {%8,%9}, {%0,%1,%2,%3};"
                 : "+f"(c[0]), "+f"(c[1]), "+f"(c[2]), "+f"(c[3])
                 : "r"(a0), "r"(a1), "r"(a2), "r"(a3), "r"(b0), "r"(b1));
}
__device__ __forceinline__ uint32_t lmaddr(uint32_t base, int row0, int pitch, int col0, int lane) {
    return base + (uint32_t)(((row0 + (lane & 15)) * pitch + col0 + ((lane >> 4) << 3)) * 2);
}
__device__ __forceinline__ void cp16(uint32_t d, const void* s) {
    asm volatile("cp.async.cg.shared.global [%0], [%1], 16;" :: "r"(d), "l"(s));
}
#define CP_COMMIT() asm volatile("cp.async.commit_group;" ::: "memory")
#define CP_WAIT0()  asm volatile("cp.async.wait_group 0;" ::: "memory")
#define CP_WAIT1()  asm volatile("cp.async.wait_group 1;" ::: "memory")

// ---------------- converters ----------------
__global__ void conv_kc(const float* __restrict__ kc) {
    int i = blockIdx.x * blockDim.x + threadIdx.x;
    if (i >= TSEQ * DLORA) return;
    g_kc_h[i] = __float2half_rn(kc[i]);
}
__global__ void conv_w(const float* __restrict__ wkv, const float* __restrict__ wuv) {
    int i = blockIdx.x * blockDim.x + threadIdx.x;
    if (i >= 4096 * DLORA) return;
    int n = i >> 9, l = i & 511;
    float x;
    if (n < 2048) x = wkv[(size_t)l * 4096 + ((n >> 7) << 8) + (n & 127)];
    else          x = wuv[(size_t)(((n - 2048) >> 7) * 512 + l) * 128 + ((n - 2048) & 127)];
    g_wt_h[i] = __float2half_rn(x);
}
__global__ void conv_rope(const float* __restrict__ kpe) {
    int i = blockIdx.x * blockDim.x + threadIdx.x;
    if (i >= TSEQ * NH * 64) return;
    int t = i >> 10, h = (i >> 6) & 15, d = i & 63;
    g_ksp[(size_t)(t * 16 + h) * 192 + 128 + d] = __float2half_rn(kpe[t * 64 + d]);
}

// ---------------- pre-GEMM: D = kc_hi @ W_hi^T, 1 term, single-stage, 2 CTA/SM ----
// smem halves: A:0  B:17408  (each 128x136); sT float staging aliases (66048 B).
#define PG_SMEM 69632
__global__ __launch_bounds__(256, 2) void pregemm() {
    extern __shared__ __align__(16) __half smh[];
    float* sT = (float*)smh;
    const uint32_t sb = smem_u32(smh);
    const uint32_t Ab = sb, Bb = sb + 17408u * 2;
    const int nt = blockIdx.x, mt = blockIdx.y;
    const int tid = threadIdx.x, lane = tid & 31, w = tid >> 5;
    const int wm = w >> 2, wn = w & 3;
    const int g = lane >> 2, t2 = lane & 3;

    float acc[4][4][4];
#pragma unroll
    for (int a = 0; a < 4; a++)
#pragma unroll
        for (int b = 0; b < 4; b++)
#pragma unroll
            for (int c = 0; c < 4; c++) acc[a][b][c] = 0.f;

    for (int chunk = 0; chunk < 4; chunk++) {
        const int kk = chunk * 128;
#pragma unroll
        for (int it = 0; it < 8; it++) {
            int idx = tid + it * 256;
            int r = idx >> 4, c = idx & 15;
            uint32_t off = (uint32_t)(r * 136 + c * 8) * 2;
            cp16(Ab + off, g_kc_h + (size_t)(mt * 128 + r) * 512 + kk + c * 8);
            cp16(Bb + off, g_wt_h + (size_t)(nt * 128 + r) * 512 + kk + c * 8);
        }
        CP_COMMIT();
        CP_WAIT0();
        __syncthreads();
#pragma unroll
        for (int ks = 0; ks < 8; ks++) {
            uint32_t af[4][4];
#pragma unroll
            for (int mf = 0; mf < 4; mf++)
                ldsm4(lmaddr(Ab, wm * 64 + mf * 16, 136, ks * 16, lane),
                      af[mf][0], af[mf][1], af[mf][2], af[mf][3]);
#pragma unroll
            for (int ng = 0; ng < 2; ng++) {
                uint32_t b0, b1, b2, b3;
                ldsm4(lmaddr(Bb, wn * 32 + ng * 16, 136, ks * 16, lane), b0, b1, b2, b3);
#pragma unroll
                for (int mf = 0; mf < 4; mf++) {
                    mma16816(acc[mf][2 * ng],     af[mf][0], af[mf][1], af[mf][2], af[mf][3], b0, b2);
                    mma16816(acc[mf][2 * ng + 1], af[mf][0], af[mf][1], af[mf][2], af[mf][3], b1, b3);
                }
            }
        }
        __syncthreads();
    }

    // stage accumulators to sT [row][col] pitch 129
#pragma unroll
    for (int mf = 0; mf < 4; mf++)
#pragma unroll
        for (int nf = 0; nf < 4; nf++) {
            int rr = wm * 64 + mf * 16 + g, cc = wn * 32 + nf * 8 + 2 * t2;
            sT[rr * 129 + cc]       = acc[mf][nf][0];
            sT[rr * 129 + cc + 1]   = acc[mf][nf][1];
            sT[(rr + 8) * 129 + cc]     = acc[mf][nf][2];
            sT[(rr + 8) * 129 + cc + 1] = acc[mf][nf][3];
        }
    __syncthreads();

    if (tid < 128) {
        if (nt < 16) {  // k_nope row tid -> g_ksp (fp16)
            size_t base = (size_t)((mt * 128 + tid) * 16 + nt) * 192;
#pragma unroll
            for (int ch = 0; ch < 4; ch++) {
                uint32_t hh[16];
#pragma unroll
                for (int i = 0; i < 16; i++)
                    hh[i] = pack2(sT[tid * 129 + ch * 32 + 2 * i], sT[tid * 129 + ch * 32 + 2 * i + 1]);
#pragma unroll
                for (int k = 0; k < 4; k++)
                    *(uint4*)(g_ksp + base + ch * 32 + k * 8) = make_uint4(hh[4*k], hh[4*k+1], hh[4*k+2], hh[4*k+3]);
            }
        } else {        // V column tid=dv -> g_vt rows (transpose, fp16)
            int h = nt - 16;
            size_t base = (size_t)(h * 128 + tid) * 2048 + mt * 128;
#pragma unroll
            for (int ch = 0; ch < 4; ch++) {
                uint32_t hh[16];
#pragma unroll
                for (int i = 0; i < 16; i++)
                    hh[i] = pack2(sT[(ch * 32 + 2 * i) * 129 + tid], sT[(ch * 32 + 2 * i + 1) * 129 + tid]);
#pragma unroll
                for (int k = 0; k < 4; k++)
                    *(uint4*)(g_vt + base + ch * 32 + k * 8) = make_uint4(hh[4*k], hh[4*k+1], hh[4*k+2], hh[4*k+3]);
            }
        }
    }
}

// ---------------- attention: 64-row q, 64-key tiles, Q in regs, 2-stage, 2 CTA/SM -
// smem halves: K0:0 (64x200) | K1:12800 | V0:25600 (128x72) | V1:34816  = 88064 B
#define AT_SMEM 88064
__global__ __launch_bounds__(128, 2) void attn(const float* __restrict__ q, float* __restrict__ out) {
    extern __shared__ __align__(16) __half smh[];
    const uint32_t sb = smem_u32(smh);
    const int qt = 31 - blockIdx.x, h = blockIdx.y;
    const int tid = threadIdx.x, lane = tid & 31, w = tid >> 5;
    const int m0 = w * 16, g = lane >> 2, t2 = lane & 3;
    const int gr0 = qt * 64 + m0 + g, gr1 = gr0 + 8;
    const int jmax = qt;   // 64-key tiles

    // stage Q into K0 buffer (fp16, prescaled by SCALE*log2e), hoist frags to regs
    for (int idx = tid; idx < 64 * 48; idx += 128) {
        int r = idx / 48, c = idx % 48;
        float4 v = *(const float4*)(q + (size_t)((qt * 64 + r) * 16 + h) * 192 + c * 4);
        *(uint2*)(smh + r * 200 + c * 4) =
            make_uint2(pack2(v.x * QS, v.y * QS), pack2(v.z * QS, v.w * QS));
    }
    __syncthreads();
    uint32_t qf[12][4];
#pragma unroll
    for (int kk = 0; kk < 12; kk++)
        ldsm4(lmaddr(sb, m0, 200, kk * 16, lane), qf[kk][0], qf[kk][1], qf[kk][2], qf[kk][3]);
    __syncthreads();

    auto prefetch = [&](int j, int buf) {
        uint32_t kb = sb + (uint32_t)buf * 12800u * 2;
        uint32_t vb = sb + (25600u + (uint32_t)buf * 9216u) * 2;
#pragma unroll
        for (int it = 0; it < 12; it++) {
            int idx = tid + it * 128;
            int r = idx / 24, c = idx % 24;
            cp16(kb + (uint32_t)(r * 200 + c * 8) * 2,
                 g_ksp + (size_t)((j * 64 + r) * 16 + h) * 192 + c * 8);
        }
#pragma unroll
        for (int it = 0; it < 8; it++) {
            int idx = tid + it * 128;
            int r = idx >> 3, c = idx & 7;
            cp16(vb + (uint32_t)(r * 72 + c * 8) * 2,
                 g_vt + (size_t)(h * 128 + r) * 2048 + j * 64 + c * 8);
        }
    };

    prefetch(0, 0); CP_COMMIT();

    float O[16][4];
#pragma unroll
    for (int f = 0; f < 16; f++)
#pragma unroll
        for (int c = 0; c < 4; c++) O[f][c] = 0.f;
    float mr0 = -INFINITY, mr1 = -INFINITY, sr0 = 0.f, sr1 = 0.f;

    for (int j = 0; j <= jmax; j++) {
        if (j < jmax) { prefetch(j + 1, (j + 1) & 1); CP_COMMIT(); CP_WAIT1(); }
        else         { CP_WAIT0(); }
        __syncthreads();
        const uint32_t sKb = sb + (uint32_t)(j & 1) * 12800u * 2;
        const uint32_t sVb = sb + (25600u + (uint32_t)(j & 1) * 9216u) * 2;

        // S = Q @ K^T (64 keys; scale folded into Q)
        float Sc[8][4];
#pragma unroll
        for (int f = 0; f < 8; f++)
#pragma unroll
            for (int c = 0; c < 4; c++) Sc[f][c] = 0.f;
#pragma unroll
        for (int kk = 0; kk < 12; kk++) {
#pragma unroll
            for (int nf2 = 0; nf2 < 4; nf2++) {
                uint32_t b0, b1, b2, b3;
                ldsm4(lmaddr(sKb, nf2 * 16, 200, kk * 16, lane), b0, b1, b2, b3);
                mma16816(Sc[2 * nf2],     qf[kk][0], qf[kk][1], qf[kk][2], qf[kk][3], b0, b2);
                mma16816(Sc[2 * nf2 + 1], qf[kk][0], qf[kk][1], qf[kk][2], qf[kk][3], b1, b3);
            }
        }

        // mask + online softmax (base-2)
        float mx0 = -INFINITY, mx1 = -INFINITY;
#pragma unroll
        for (int f = 0; f < 8; f++) {
            int c0 = j * 64 + f * 8 + t2 * 2;
            float x0 = (c0     <= gr0) ? Sc[f][0] : -INFINITY;
            float x1 = (c0 + 1 <= gr0) ? Sc[f][1] : -INFINITY;
            float x2 = (c0     <= gr1) ? Sc[f][2] : -INFINITY;
            float x3 = (c0 + 1 <= gr1) ? Sc[f][3] : -INFINITY;
            Sc[f][0] = x0; Sc[f][1] = x1; Sc[f][2] = x2; Sc[f][3] = x3;
            mx0 = fmaxf(mx0, fmaxf(x0, x1));
            mx1 = fmaxf(mx1, fmaxf(x2, x3));
        }
        mx0 = fmaxf(mx0, __shfl_xor_sync(0xffffffffu, mx0, 1));
        mx0 = fmaxf(mx0, __shfl_xor_sync(0xffffffffu, mx0, 2));
        mx1 = fmaxf(mx1, __shfl_xor_sync(0xffffffffu, mx1, 1));
        mx1 = fmaxf(mx1, __shfl_xor_sync(0xffffffffu, mx1, 2));
        float mn0 = fmaxf(mr0, mx0), mn1 = fmaxf(mr1, mx1);
        float al0 = exp2f(mr0 - mn0), al1 = exp2f(mr1 - mn1);

        float rs0 = 0.f, rs1 = 0.f;
        uint32_t Pa[8], Pb[8];
#pragma unroll
        for (int f = 0; f < 8; f++) {
            float e0 = exp2f(Sc[f][0] - mn0), e1 = exp2f(Sc[f][1] - mn0);
            float e2 = exp2f(Sc[f][2] - mn1), e3 = exp2f(Sc[f][3] - mn1);
            rs0 += e0 + e1; rs1 += e2 + e3;
            Pa[f] = pack2(e0, e1); Pb[f] = pack2(e2, e3);
        }
        rs0 += __shfl_xor_sync(0xffffffffu, rs0, 1);
        rs0 += __shfl_xor_sync(0xffffffffu, rs0, 2);
        rs1 += __shfl_xor_sync(0xffffffffu, rs1, 1);
        rs1 += __shfl_xor_sync(0xffffffffu, rs1, 2);
        sr0 = sr0 * al0 + rs0; sr1 = sr1 * al1 + rs1;
        mr0 = mn0; mr1 = mn1;
#pragma unroll
        for (int f = 0; f < 16; f++) {
            O[f][0] *= al0; O[f][1] *= al0; O[f][2] *= al1; O[f][3] *= al1;
        }

        // O += P @ V   (4 k-steps of 16)
#pragma unroll
        for (int kc2 = 0; kc2 < 4; kc2++) {
            uint32_t a0 = Pa[2 * kc2], a1 = Pb[2 * kc2], a2 = Pa[2 * kc2 + 1], a3 = Pb[2 * kc2 + 1];
#pragma unroll
            for (int nf2 = 0; nf2 < 8; nf2++) {
                uint32_t b0, b1, b2, b3;
                ldsm4(lmaddr(sVb, nf2 * 16, 72, kc2 * 16, lane), b0, b1, b2, b3);
                mma16816(O[2 * nf2],     a0, a1, a2, a3, b0, b2);
                mma16816(O[2 * nf2 + 1], a0, a1, a2, a3, b1, b3);
            }
        }
        __syncthreads();
    }

    // epilogue
    float inv0 = 1.f / sr0, inv1 = 1.f / sr1;
#pragma unroll
    for (int f = 0; f < 16; f++) {
        int col = h * 128 + f * 8 + t2 * 2;
        *(float2*)(out + (size_t)gr0 * 2048 + col) = make_float2(O[f][0] * inv0, O[f][1] * inv0);
        *(float2*)(out + (size_t)gr1 * 2048 + col) = make_float2(O[f][2] * inv1, O[f][3] * inv1);
    }
}

// ---------------------------------------------------------------------------
extern "C" void kernel_launch(void* const* d_in, const int* in_sizes, int n_in,
                              void* d_out, int out_size) {
    (void)in_sizes; (void)n_in; (void)out_size;
    const float* q   = (const float*)d_in[0];
    const float* kc  = (const float*)d_in[1];
    const float* kpe = (const float*)d_in[2];
    const float* wkv = (const float*)d_in[3];
    const float* wuv = (const float*)d_in[4];
    float* out = (float*)d_out;

    conv_kc  <<<(TSEQ * DLORA + 255) / 256, 256>>>(kc);
    conv_w   <<<(4096 * DLORA + 255) / 256, 256>>>(wkv, wuv);
    conv_rope<<<(TSEQ * NH * 64 + 255) / 256, 256>>>(kpe);

    cudaFuncSetAttribute(pregemm, cudaFuncAttributeMaxDynamicSharedMemorySize, PG_SMEM);
    cudaFuncSetAttribute(attn,    cudaFuncAttributeMaxDynamicSharedMemorySize, AT_SMEM);

    pregemm<<<dim3(32, 16), 256, PG_SMEM>>>();
    attn<<<dim3(32, 16), 128, AT_SMEM>>>(q, out);
}

// round 9
// speedup vs baseline: 23.4882x; 1.0110x over previous
#include <cuda_runtime.h>
#include <cuda_fp16.h>
#include <math.h>
#include <stdint.h>

#define TSEQ   2048
#define NH     16
#define DLORA  512
// SCALE * log2(e)
#define QS      0.1041277131f
#define MASKVAL (-30000.f)

// ---------------- scratch (device globals; allocation-free) ----------------
__device__ __half g_kc_h[TSEQ * DLORA];          // [t][l]
__device__ __half g_wt_h[4096 * DLORA];          // [n][l] combined weight^T
__device__ __half g_ksp[TSEQ * NH * 192];        // [t][h][ nope(128)|rope(64) ]
__device__ __half g_vt[NH * 128 * TSEQ];         // [h][dv][t]

// ---------------- helpers ----------------
__device__ __forceinline__ uint32_t smem_u32(const void* p) {
    uint32_t a;
    asm("{ .reg .u64 t; cvta.to.shared.u64 t, %1; cvt.u32.u64 %0, t; }" : "=r"(a) : "l"(p));
    return a;
}
__device__ __forceinline__ uint32_t pack2(float a, float b) {
    __half2 h = __floats2half2_rn(a, b);
    return *reinterpret_cast<uint32_t*>(&h);
}
__device__ __forceinline__ uint32_t hexp2(uint32_t h) {
    uint32_t r;
    asm("ex2.approx.f16x2 %0, %1;" : "=r"(r) : "r"(h));
    return r;
}
__device__ __forceinline__ void ldsm4(uint32_t a, uint32_t& r0, uint32_t& r1, uint32_t& r2, uint32_t& r3) {
    asm volatile("ldmatrix.sync.aligned.m8n8.x4.shared.b16 {%0,%1,%2,%3}, [%4];"
                 : "=r"(r0), "=r"(r1), "=r"(r2), "=r"(r3) : "r"(a));
}
__device__ __forceinline__ void mma16816(float* c, uint32_t a0, uint32_t a1, uint32_t a2, uint32_t a3,
                                         uint32_t b0, uint32_t b1) {
    asm volatile("mma.sync.aligned.m16n8k16.row.col.f32.f16.f16.f32 "
                 "{%0,%1,%2,%3}, {%4,%5,%6,%7}, {%8,%9}, {%0,%1,%2,%3};"
                 : "+f"(c[0]), "+f"(c[1]), "+f"(c[2]), "+f"(c[3])
                 : "r"(a0), "r"(a1), "r"(a2), "r"(a3), "r"(b0), "r"(b1));
}
__device__ __forceinline__ uint32_t lmaddr(uint32_t base, int row0, int pitch, int col0, int lane) {
    return base + (uint32_t)(((row0 + (lane & 15)) * pitch + col0 + ((lane >> 4) << 3)) * 2);
}
__device__ __forceinline__ void cp16(uint32_t d, const void* s) {
    asm volatile("cp.async.cg.shared.global [%0], [%1], 16;" :: "r"(d), "l"(s));
}
#define CP_COMMIT() asm volatile("cp.async.commit_group;" ::: "memory")
#define CP_WAIT0()  asm volatile("cp.async.wait_group 0;" ::: "memory")
#define CP_WAIT1()  asm volatile("cp.async.wait_group 1;" ::: "memory")

// ---------------- fused converter ----------------
__global__ void conv_all(const float* __restrict__ kc, const float* __restrict__ kpe,
                         const float* __restrict__ wkv, const float* __restrict__ wuv) {
    int i = blockIdx.x * blockDim.x + threadIdx.x;
    if (i < 4096 * DLORA) {
        int n = i >> 9, l = i & 511;
        float x;
        if (n < 2048) x = wkv[(size_t)l * 4096 + ((n >> 7) << 8) + (n & 127)];
        else          x = wuv[(size_t)(((n - 2048) >> 7) * 512 + l) * 128 + ((n - 2048) & 127)];
        g_wt_h[i] = __float2half_rn(x);
    }
    if (i < TSEQ * DLORA) g_kc_h[i] = __float2half_rn(kc[i]);
    if (i < TSEQ * NH * 64) {
        int t = i >> 10, h = (i >> 6) & 15, d = i & 63;
        g_ksp[(size_t)(t * 16 + h) * 192 + 128 + d] = __float2half_rn(kpe[t * 64 + d]);
    }
}

// ---------------- pre-GEMM: D = kc_hi @ W_hi^T, 1 term, single-stage, 2 CTA/SM ----
#define PG_SMEM 69632
__global__ __launch_bounds__(256, 2) void pregemm() {
    extern __shared__ __align__(16) __half smh[];
    float* sT = (float*)smh;
    const uint32_t sb = smem_u32(smh);
    const uint32_t Ab = sb, Bb = sb + 17408u * 2;
    const int nt = blockIdx.x, mt = blockIdx.y;
    const int tid = threadIdx.x, lane = tid & 31, w = tid >> 5;
    const int wm = w >> 2, wn = w & 3;
    const int g = lane >> 2, t2 = lane & 3;

    float acc[4][4][4];
#pragma unroll
    for (int a = 0; a < 4; a++)
#pragma unroll
        for (int b = 0; b < 4; b++)
#pragma unroll
            for (int c = 0; c < 4; c++) acc[a][b][c] = 0.f;

    for (int chunk = 0; chunk < 4; chunk++) {
        const int kk = chunk * 128;
#pragma unroll
        for (int it = 0; it < 8; it++) {
            int idx = tid + it * 256;
            int r = idx >> 4, c = idx & 15;
            uint32_t off = (uint32_t)(r * 136 + c * 8) * 2;
            cp16(Ab + off, g_kc_h + (size_t)(mt * 128 + r) * 512 + kk + c * 8);
            cp16(Bb + off, g_wt_h + (size_t)(nt * 128 + r) * 512 + kk + c * 8);
        }
        CP_COMMIT();
        CP_WAIT0();
        __syncthreads();
#pragma unroll
        for (int ks = 0; ks < 8; ks++) {
            uint32_t af[4][4];
#pragma unroll
            for (int mf = 0; mf < 4; mf++)
                ldsm4(lmaddr(Ab, wm * 64 + mf * 16, 136, ks * 16, lane),
                      af[mf][0], af[mf][1], af[mf][2], af[mf][3]);
#pragma unroll
            for (int ng = 0; ng < 2; ng++) {
                uint32_t b0, b1, b2, b3;
                ldsm4(lmaddr(Bb, wn * 32 + ng * 16, 136, ks * 16, lane), b0, b1, b2, b3);
#pragma unroll
                for (int mf = 0; mf < 4; mf++) {
                    mma16816(acc[mf][2 * ng],     af[mf][0], af[mf][1], af[mf][2], af[mf][3], b0, b2);
                    mma16816(acc[mf][2 * ng + 1], af[mf][0], af[mf][1], af[mf][2], af[mf][3], b1, b3);
                }
            }
        }
        __syncthreads();
    }

#pragma unroll
    for (int mf = 0; mf < 4; mf++)
#pragma unroll
        for (int nf = 0; nf < 4; nf++) {
            int rr = wm * 64 + mf * 16 + g, cc = wn * 32 + nf * 8 + 2 * t2;
            sT[rr * 129 + cc]       = acc[mf][nf][0];
            sT[rr * 129 + cc + 1]   = acc[mf][nf][1];
            sT[(rr + 8) * 129 + cc]     = acc[mf][nf][2];
            sT[(rr + 8) * 129 + cc + 1] = acc[mf][nf][3];
        }
    __syncthreads();

    if (tid < 128) {
        if (nt < 16) {
            size_t base = (size_t)((mt * 128 + tid) * 16 + nt) * 192;
#pragma unroll
            for (int ch = 0; ch < 4; ch++) {
                uint32_t hh[16];
#pragma unroll
                for (int i = 0; i < 16; i++)
                    hh[i] = pack2(sT[tid * 129 + ch * 32 + 2 * i], sT[tid * 129 + ch * 32 + 2 * i + 1]);
#pragma unroll
                for (int k = 0; k < 4; k++)
                    *(uint4*)(g_ksp + base + ch * 32 + k * 8) = make_uint4(hh[4*k], hh[4*k+1], hh[4*k+2], hh[4*k+3]);
            }
        } else {
            int h = nt - 16;
            size_t base = (size_t)(h * 128 + tid) * 2048 + mt * 128;
#pragma unroll
            for (int ch = 0; ch < 4; ch++) {
                uint32_t hh[16];
#pragma unroll
                for (int i = 0; i < 16; i++)
                    hh[i] = pack2(sT[(ch * 32 + 2 * i) * 129 + tid], sT[(ch * 32 + 2 * i + 1) * 129 + tid]);
#pragma unroll
                for (int k = 0; k < 4; k++)
                    *(uint4*)(g_vt + base + ch * 32 + k * 8) = make_uint4(hh[4*k], hh[4*k+1], hh[4*k+2], hh[4*k+3]);
            }
        }
    }
}

// ---------------- attention ------------------------------------------------
// smem (halfs): K0:0 (64x200) | K1:12800 | V0:25600 (144x72) | V1:35968  = 92672 B
// V rows 0..127 = V^T, row 128 = ones (row-sum via MMA), 129..143 = padding.
#define AT_SMEM 92672
__global__ __launch_bounds__(128, 2) void attn(const float* __restrict__ q, float* __restrict__ out) {
    extern __shared__ __align__(16) __half smh[];
    const uint32_t sb = smem_u32(smh);
    const int qt = 31 - blockIdx.x, h = blockIdx.y;
    const int tid = threadIdx.x, lane = tid & 31, w = tid >> 5;
    const int m0 = w * 16, g = lane >> 2, t2 = lane & 3;
    const int gr0 = qt * 64 + m0 + g, gr1 = gr0 + 8;
    const int jmax = qt;

    // ones/zero rows (128..135) of both V buffers
    for (int idx = tid; idx < 2 * 8 * 72; idx += 128) {
        int b = idx / (8 * 72), rem = idx % (8 * 72);
        int r = rem / 72, c = rem % 72;
        smh[25600 + b * 10368 + (128 + r) * 72 + c] =
            (r == 0 && c < 64) ? __float2half(1.f) : __float2half(0.f);
    }
    // stage Q into K0 buffer (prescaled), hoist frags
    for (int idx = tid; idx < 64 * 48; idx += 128) {
        int r = idx / 48, c = idx % 48;
        float4 v = *(const float4*)(q + (size_t)((qt * 64 + r) * 16 + h) * 192 + c * 4);
        *(uint2*)(smh + r * 200 + c * 4) =
            make_uint2(pack2(v.x * QS, v.y * QS), pack2(v.z * QS, v.w * QS));
    }
    __syncthreads();
    uint32_t qf[12][4];
#pragma unroll
    for (int kk = 0; kk < 12; kk++)
        ldsm4(lmaddr(sb, m0, 200, kk * 16, lane), qf[kk][0], qf[kk][1], qf[kk][2], qf[kk][3]);
    __syncthreads();

    auto prefetch = [&](int j, int buf) {
        uint32_t kb = sb + (uint32_t)buf * 12800u * 2;
        uint32_t vb = sb + (25600u + (uint32_t)buf * 10368u) * 2;
#pragma unroll
        for (int it = 0; it < 12; it++) {
            int idx = tid + it * 128;
            int r = idx / 24, c = idx % 24;
            cp16(kb + (uint32_t)(r * 200 + c * 8) * 2,
                 g_ksp + (size_t)((j * 64 + r) * 16 + h) * 192 + c * 8);
        }
#pragma unroll
        for (int it = 0; it < 8; it++) {
            int idx = tid + it * 128;
            int r = idx >> 3, c = idx & 7;
            cp16(vb + (uint32_t)(r * 72 + c * 8) * 2,
                 g_vt + (size_t)(h * 128 + r) * 2048 + j * 64 + c * 8);
        }
    };

    prefetch(0, 0); CP_COMMIT();

    float O[16][4], Osum[4];
#pragma unroll
    for (int f = 0; f < 16; f++)
#pragma unroll
        for (int c = 0; c < 4; c++) O[f][c] = 0.f;
#pragma unroll
    for (int c = 0; c < 4; c++) Osum[c] = 0.f;
    float mr0 = -INFINITY, mr1 = -INFINITY;

    for (int j = 0; j <= jmax; j++) {
        if (j < jmax) { prefetch(j + 1, (j + 1) & 1); CP_COMMIT(); CP_WAIT1(); }
        else         { CP_WAIT0(); }
        __syncthreads();
        const uint32_t sKb = sb + (uint32_t)(j & 1) * 12800u * 2;
        const uint32_t sVb = sb + (25600u + (uint32_t)(j & 1) * 10368u) * 2;

        // S = Q @ K^T
        float Sc[8][4];
#pragma unroll
        for (int f = 0; f < 8; f++)
#pragma unroll
            for (int c = 0; c < 4; c++) Sc[f][c] = 0.f;
#pragma unroll
        for (int kk = 0; kk < 12; kk++) {
#pragma unroll
            for (int nf2 = 0; nf2 < 4; nf2++) {
                uint32_t b0, b1, b2, b3;
                ldsm4(lmaddr(sKb, nf2 * 16, 200, kk * 16, lane), b0, b1, b2, b3);
                mma16816(Sc[2 * nf2],     qf[kk][0], qf[kk][1], qf[kk][2], qf[kk][3], b0, b2);
                mma16816(Sc[2 * nf2 + 1], qf[kk][0], qf[kk][1], qf[kk][2], qf[kk][3], b1, b3);
            }
        }

        // mask only on diagonal tile
        if (j == jmax) {
#pragma unroll
            for (int f = 0; f < 8; f++) {
                int c0 = j * 64 + f * 8 + t2 * 2;
                Sc[f][0] = (c0     <= gr0) ? Sc[f][0] : MASKVAL;
                Sc[f][1] = (c0 + 1 <= gr0) ? Sc[f][1] : MASKVAL;
                Sc[f][2] = (c0     <= gr1) ? Sc[f][2] : MASKVAL;
                Sc[f][3] = (c0 + 1 <= gr1) ? Sc[f][3] : MASKVAL;
            }
        }
        // row max
        float mx0 = -INFINITY, mx1 = -INFINITY;
#pragma unroll
        for (int f = 0; f < 8; f++) {
            mx0 = fmaxf(mx0, fmaxf(Sc[f][0], Sc[f][1]));
            mx1 = fmaxf(mx1, fmaxf(Sc[f][2], Sc[f][3]));
        }
        mx0 = fmaxf(mx0, __shfl_xor_sync(0xffffffffu, mx0, 1));
        mx0 = fmaxf(mx0, __shfl_xor_sync(0xffffffffu, mx0, 2));
        mx1 = fmaxf(mx1, __shfl_xor_sync(0xffffffffu, mx1, 1));
        mx1 = fmaxf(mx1, __shfl_xor_sync(0xffffffffu, mx1, 2));
        float mn0 = fmaxf(mr0, mx0), mn1 = fmaxf(mr1, mx1);
        float al0 = exp2f(mr0 - mn0), al1 = exp2f(mr1 - mn1);
        mr0 = mn0; mr1 = mn1;

        // rescale O (+ sum) only when max moved
        if (!__all_sync(0xffffffffu, (al0 == 1.f) & (al1 == 1.f))) {
#pragma unroll
            for (int f = 0; f < 16; f++) {
                O[f][0] *= al0; O[f][1] *= al0; O[f][2] *= al1; O[f][3] *= al1;
            }
            Osum[0] *= al0; Osum[1] *= al0; Osum[2] *= al1; Osum[3] *= al1;
        }

        // P = 2^(S - mn) in fp16 (ex2.approx.f16x2)
        uint32_t Pa[8], Pb[8];
#pragma unroll
        for (int f = 0; f < 8; f++) {
            Pa[f] = hexp2(pack2(Sc[f][0] - mn0, Sc[f][1] - mn0));
            Pb[f] = hexp2(pack2(Sc[f][2] - mn1, Sc[f][3] - mn1));
        }

        // O += P @ V  (and row-sum via ones row)
#pragma unroll
        for (int kc2 = 0; kc2 < 4; kc2++) {
            uint32_t a0 = Pa[2 * kc2], a1 = Pb[2 * kc2], a2 = Pa[2 * kc2 + 1], a3 = Pb[2 * kc2 + 1];
#pragma unroll
            for (int nf2 = 0; nf2 < 8; nf2++) {
                uint32_t b0, b1, b2, b3;
                ldsm4(lmaddr(sVb, nf2 * 16, 72, kc2 * 16, lane), b0, b1, b2, b3);
                mma16816(O[2 * nf2],     a0, a1, a2, a3, b0, b2);
                mma16816(O[2 * nf2 + 1], a0, a1, a2, a3, b1, b3);
            }
            {   // sum column (V rows 128..143; only row 128 = ones matters)
                uint32_t b0, b1, b2, b3;
                ldsm4(lmaddr(sVb, 128, 72, kc2 * 16, lane), b0, b1, b2, b3);
                mma16816(Osum, a0, a1, a2, a3, b0, b2);
            }
        }
        __syncthreads();
    }

    // epilogue: sums live at col 128 -> t2==0 lanes; broadcast within 4-lane group
    float sum0 = __shfl_sync(0xffffffffu, Osum[0], lane & ~3);
    float sum1 = __shfl_sync(0xffffffffu, Osum[2], lane & ~3);
    float inv0 = 1.f / sum0, inv1 = 1.f / sum1;
#pragma unroll
    for (int f = 0; f < 16; f++) {
        int col = h * 128 + f * 8 + t2 * 2;
        *(float2*)(out + (size_t)gr0 * 2048 + col) = make_float2(O[f][0] * inv0, O[f][1] * inv0);
        *(float2*)(out + (size_t)gr1 * 2048 + col) = make_float2(O[f][2] * inv1, O[f][3] * inv1);
    }
}

// ---------------------------------------------------------------------------
extern "C" void kernel_launch(void* const* d_in, const int* in_sizes, int n_in,
                              void* d_out, int out_size) {
    (void)in_sizes; (void)n_in; (void)out_size;
    const float* q   = (const float*)d_in[0];
    const float* kc  = (const float*)d_in[1];
    const float* kpe = (const float*)d_in[2];
    const float* wkv = (const float*)d_in[3];
    const float* wuv = (const float*)d_in[4];
    float* out = (float*)d_out;

    conv_all<<<(4096 * DLORA + 255) / 256, 256>>>(kc, kpe, wkv, wuv);

    cudaFuncSetAttribute(pregemm, cudaFuncAttributeMaxDynamicSharedMemorySize, PG_SMEM);
    cudaFuncSetAttribute(attn,    cudaFuncAttributeMaxDynamicSharedMemorySize, AT_SMEM);

    pregemm<<<dim3(32, 16), 256, PG_SMEM>>>();
    attn<<<dim3(32, 16), 128, AT_SMEM>>>(q, out);
}

// round 10
// speedup vs baseline: 24.9050x; 1.0603x over previous
#include <cuda_runtime.h>
#include <cuda_fp16.h>
#include <math.h>
#include <stdint.h>

#define TSEQ   2048
#define NH     16
#define DLORA  512
// SCALE * log2(e)
#define QS      0.1041277131f
#define MASKVAL (-30000.f)

// ---------------- scratch (device globals; allocation-free) ----------------
__device__ __half g_kc_h[TSEQ * DLORA];          // [t][l]
__device__ __half g_wt_h[4096 * DLORA];          // [n][l] combined weight^T
__device__ __half g_ksp[TSEQ * NH * 192];        // [t][h][ nope(128)|rope(64) ]
__device__ __half g_vt[NH * 128 * TSEQ];         // [h][dv][t]

// ---------------- helpers ----------------
__device__ __forceinline__ uint32_t smem_u32(const void* p) {
    uint32_t a;
    asm("{ .reg .u64 t; cvta.to.shared.u64 t, %1; cvt.u32.u64 %0, t; }" : "=r"(a) : "l"(p));
    return a;
}
__device__ __forceinline__ uint32_t pack2(float a, float b) {
    __half2 h = __floats2half2_rn(a, b);
    return *reinterpret_cast<uint32_t*>(&h);
}
__device__ __forceinline__ uint32_t hexp2(uint32_t h) {
    uint32_t r;
    asm("ex2.approx.f16x2 %0, %1;" : "=r"(r) : "r"(h));
    return r;
}
__device__ __forceinline__ void ldsm4(uint32_t a, uint32_t& r0, uint32_t& r1, uint32_t& r2, uint32_t& r3) {
    asm volatile("ldmatrix.sync.aligned.m8n8.x4.shared.b16 {%0,%1,%2,%3}, [%4];"
                 : "=r"(r0), "=r"(r1), "=r"(r2), "=r"(r3) : "r"(a));
}
__device__ __forceinline__ void mma16816(float* c, uint32_t a0, uint32_t a1, uint32_t a2, uint32_t a3,
                                         uint32_t b0, uint32_t b1) {
    asm volatile("mma.sync.aligned.m16n8k16.row.col.f32.f16.f16.f32 "
                 "{%0,%1,%2,%3}, {%4,%5,%6,%7}, {%8,%9}, {%0,%1,%2,%3};"
                 : "+f"(c[0]), "+f"(c[1]), "+f"(c[2]), "+f"(c[3])
                 : "r"(a0), "r"(a1), "r"(a2), "r"(a3), "r"(b0), "r"(b1));
}
__device__ __forceinline__ uint32_t lmaddr(uint32_t base, int row0, int pitch, int col0, int lane) {
    return base + (uint32_t)(((row0 + (lane & 15)) * pitch + col0 + ((lane >> 4) << 3)) * 2);
}
__device__ __forceinline__ void cp16(uint32_t d, const void* s) {
    asm volatile("cp.async.cg.shared.global [%0], [%1], 16;" :: "r"(d), "l"(s));
}
#define CP_COMMIT() asm volatile("cp.async.commit_group;" ::: "memory")
#define CP_WAIT0()  asm volatile("cp.async.wait_group 0;" ::: "memory")

// ---------------- converters ----------------
// W transpose: tiled through smem. Block = 128 n x 32 l.
__global__ __launch_bounds__(256) void conv_w_t(const float* __restrict__ wkv,
                                                const float* __restrict__ wuv) {
    __shared__ __half sW[32][130];
    const int nt = blockIdx.x;   // 0..31 -> n tile of 128
    const int lt = blockIdx.y;   // 0..15 -> l tile of 32
    const int tid = threadIdx.x;
    const bool isW = nt < 16;
#pragma unroll
    for (int it = 0; it < 16; it++) {
        int idx = tid + it * 256;
        int nl = idx & 127, ll = idx >> 7;
        int l = lt * 32 + ll;
        float x;
        if (isW) x = wkv[(size_t)l * 4096 + nt * 256 + nl];
        else     x = wuv[(size_t)(nt - 16) * 65536 + (size_t)l * 128 + nl];
        sW[ll][nl] = __float2half_rn(x);
    }
    __syncthreads();
    int ll = tid & 31;
    int n0 = (tid >> 5) * 16;
#pragma unroll
    for (int i = 0; i < 16; i++) {
        int n = n0 + i;
        g_wt_h[(size_t)(nt * 128 + n) * 512 + lt * 32 + ll] = sW[ll][n];
    }
}
// kc (vectorized) + rope broadcast
__global__ void conv_misc(const float* __restrict__ kc, const float* __restrict__ kpe) {
    int i = blockIdx.x * blockDim.x + threadIdx.x;   // 1M threads
    if (i < TSEQ * DLORA / 4) {
        float4 v = *(const float4*)(kc + (size_t)i * 4);
        *(uint2*)(g_kc_h + (size_t)i * 4) = make_uint2(pack2(v.x, v.y), pack2(v.z, v.w));
    }
    {   // rope: t (11b) x h (4b) x d2 (5b)
        int t = i >> 9, h = (i >> 5) & 15, d2 = i & 31;
        float2 v = *(const float2*)(kpe + t * 64 + d2 * 2);
        *(uint32_t*)(g_ksp + (size_t)(t * 16 + h) * 192 + 128 + d2 * 2) = pack2(v.x, v.y);
    }
}

// ---------------- pre-GEMM: D = kc_hi @ W_hi^T, 1 term, single-stage, 2 CTA/SM ----
#define PG_SMEM 69632
__global__ __launch_bounds__(256, 2) void pregemm() {
    extern __shared__ __align__(16) __half smh[];
    float* sT = (float*)smh;
    const uint32_t sb = smem_u32(smh);
    const uint32_t Ab = sb, Bb = sb + 17408u * 2;
    const int nt = blockIdx.x, mt = blockIdx.y;
    const int tid = threadIdx.x, lane = tid & 31, w = tid >> 5;
    const int wm = w >> 2, wn = w & 3;
    const int g = lane >> 2, t2 = lane & 3;

    float acc[4][4][4];
#pragma unroll
    for (int a = 0; a < 4; a++)
#pragma unroll
        for (int b = 0; b < 4; b++)
#pragma unroll
            for (int c = 0; c < 4; c++) acc[a][b][c] = 0.f;

    for (int chunk = 0; chunk < 4; chunk++) {
        const int kk = chunk * 128;
#pragma unroll
        for (int it = 0; it < 8; it++) {
            int idx = tid + it * 256;
            int r = idx >> 4, c = idx & 15;
            uint32_t off = (uint32_t)(r * 136 + c * 8) * 2;
            cp16(Ab + off, g_kc_h + (size_t)(mt * 128 + r) * 512 + kk + c * 8);
            cp16(Bb + off, g_wt_h + (size_t)(nt * 128 + r) * 512 + kk + c * 8);
        }
        CP_COMMIT();
        CP_WAIT0();
        __syncthreads();
#pragma unroll
        for (int ks = 0; ks < 8; ks++) {
            uint32_t af[4][4];
#pragma unroll
            for (int mf = 0; mf < 4; mf++)
                ldsm4(lmaddr(Ab, wm * 64 + mf * 16, 136, ks * 16, lane),
                      af[mf][0], af[mf][1], af[mf][2], af[mf][3]);
#pragma unroll
            for (int ng = 0; ng < 2; ng++) {
                uint32_t b0, b1, b2, b3;
                ldsm4(lmaddr(Bb, wn * 32 + ng * 16, 136, ks * 16, lane), b0, b1, b2, b3);
#pragma unroll
                for (int mf = 0; mf < 4; mf++) {
                    mma16816(acc[mf][2 * ng],     af[mf][0], af[mf][1], af[mf][2], af[mf][3], b0, b2);
                    mma16816(acc[mf][2 * ng + 1], af[mf][0], af[mf][1], af[mf][2], af[mf][3], b1, b3);
                }
            }
        }
        __syncthreads();
    }

#pragma unroll
    for (int mf = 0; mf < 4; mf++)
#pragma unroll
        for (int nf = 0; nf < 4; nf++) {
            int rr = wm * 64 + mf * 16 + g, cc = wn * 32 + nf * 8 + 2 * t2;
            sT[rr * 129 + cc]       = acc[mf][nf][0];
            sT[rr * 129 + cc + 1]   = acc[mf][nf][1];
            sT[(rr + 8) * 129 + cc]     = acc[mf][nf][2];
            sT[(rr + 8) * 129 + cc + 1] = acc[mf][nf][3];
        }
    __syncthreads();

    if (tid < 128) {
        if (nt < 16) {
            size_t base = (size_t)((mt * 128 + tid) * 16 + nt) * 192;
#pragma unroll
            for (int ch = 0; ch < 4; ch++) {
                uint32_t hh[16];
#pragma unroll
                for (int i = 0; i < 16; i++)
                    hh[i] = pack2(sT[tid * 129 + ch * 32 + 2 * i], sT[tid * 129 + ch * 32 + 2 * i + 1]);
#pragma unroll
                for (int k = 0; k < 4; k++)
                    *(uint4*)(g_ksp + base + ch * 32 + k * 8) = make_uint4(hh[4*k], hh[4*k+1], hh[4*k+2], hh[4*k+3]);
            }
        } else {
            int h = nt - 16;
            size_t base = (size_t)(h * 128 + tid) * 2048 + mt * 128;
#pragma unroll
            for (int ch = 0; ch < 4; ch++) {
                uint32_t hh[16];
#pragma unroll
                for (int i = 0; i < 16; i++)
                    hh[i] = pack2(sT[(ch * 32 + 2 * i) * 129 + tid], sT[(ch * 32 + 2 * i + 1) * 129 + tid]);
#pragma unroll
                for (int k = 0; k < 4; k++)
                    *(uint4*)(g_vt + base + ch * 32 + k * 8) = make_uint4(hh[4*k], hh[4*k+1], hh[4*k+2], hh[4*k+3]);
            }
        }
    }
}

// ---------------- attention ------------------------------------------------
// 64 q-rows/CTA, 128-key LOGICAL tiles = 2x 64-key subs. K: 2 bufs; V: ring of 3.
// smem (halfs): K0:0 (64x200) | K1:12800 | V0:25600 (144x72) | V1:35968 | V2:46336
// total = 56704 halves = 113408 B. 2 CTA/SM (226816 <= 228KB).
#define AT_SMEM 113408
#define VBASE   25600u
#define VSZ     10368u
__global__ __launch_bounds__(128, 2) void attn(const float* __restrict__ q, float* __restrict__ out) {
    extern __shared__ __align__(16) __half smh[];
    const uint32_t sb = smem_u32(smh);
    const int qt = 31 - blockIdx.x, h = blockIdx.y;
    const int tid = threadIdx.x, lane = tid & 31, w = tid >> 5;
    const int m0 = w * 16, g = lane >> 2, t2 = lane & 3;
    const int gr0 = qt * 64 + m0 + g, gr1 = gr0 + 8;
    const int smax = qt;                       // last 64-key sub-tile

    // ones rows (128..135) of all 3 V buffers
    for (int idx = tid; idx < 3 * 8 * 72; idx += 128) {
        int b = idx / (8 * 72), rem = idx % (8 * 72);
        int r = rem / 72, c = rem % 72;
        smh[VBASE + b * VSZ + (128 + r) * 72 + c] =
            (r == 0 && c < 64) ? __float2half(1.f) : __float2half(0.f);
    }
    // stage Q into K0 (prescaled), hoist frags to regs
    for (int idx = tid; idx < 64 * 48; idx += 128) {
        int r = idx / 48, c = idx % 48;
        float4 v = *(const float4*)(q + (size_t)((qt * 64 + r) * 16 + h) * 192 + c * 4);
        *(uint2*)(smh + r * 200 + c * 4) =
            make_uint2(pack2(v.x * QS, v.y * QS), pack2(v.z * QS, v.w * QS));
    }
    __syncthreads();
    uint32_t qf[12][4];
#pragma unroll
    for (int kk = 0; kk < 12; kk++)
        ldsm4(lmaddr(sb, m0, 200, kk * 16, lane), qf[kk][0], qf[kk][1], qf[kk][2], qf[kk][3]);
    __syncthreads();

    auto prefK = [&](int s) {
        uint32_t kb = sb + (uint32_t)(s & 1) * 12800u * 2;
#pragma unroll
        for (int it = 0; it < 12; it++) {
            int idx = tid + it * 128;
            int r = idx / 24, c = idx % 24;
            cp16(kb + (uint32_t)(r * 200 + c * 8) * 2,
                 g_ksp + (size_t)((s * 64 + r) * 16 + h) * 192 + c * 8);
        }
    };
    auto prefV = [&](int s) {
        uint32_t vb = sb + (VBASE + (uint32_t)(s % 3) * VSZ) * 2;
#pragma unroll
        for (int it = 0; it < 8; it++) {
            int idx = tid + it * 128;
            int r = idx >> 3, c = idx & 7;
            cp16(vb + (uint32_t)(r * 72 + c * 8) * 2,
                 g_vt + (size_t)(h * 128 + r) * 2048 + s * 64 + c * 8);
        }
    };

    prefK(0); prefV(0);
    if (1 <= smax) { prefK(1); prefV(1); }
    CP_COMMIT();

    float O[16][4], Osum[4];
#pragma unroll
    for (int f = 0; f < 16; f++)
#pragma unroll
        for (int c = 0; c < 4; c++) O[f][c] = 0.f;
#pragma unroll
    for (int c = 0; c < 4; c++) Osum[c] = 0.f;
    float mr0 = -INFINITY, mr1 = -INFINITY;

    for (int s0 = 0; s0 <= smax; s0 += 2) {
        const bool has_b = (s0 + 1 <= smax);
        CP_WAIT0();
        __syncthreads();

        // ---- S over up to 128 keys ----
        float Sc[16][4];
#pragma unroll
        for (int f = 0; f < 16; f++)
#pragma unroll
            for (int c = 0; c < 4; c++) Sc[f][c] = 0.f;
        {
            const uint32_t kb0 = sb;
#pragma unroll
            for (int kk = 0; kk < 12; kk++)
#pragma unroll
                for (int nf2 = 0; nf2 < 4; nf2++) {
                    uint32_t b0, b1, b2, b3;
                    ldsm4(lmaddr(kb0, nf2 * 16, 200, kk * 16, lane), b0, b1, b2, b3);
                    mma16816(Sc[2 * nf2],     qf[kk][0], qf[kk][1], qf[kk][2], qf[kk][3], b0, b2);
                    mma16816(Sc[2 * nf2 + 1], qf[kk][0], qf[kk][1], qf[kk][2], qf[kk][3], b1, b3);
                }
        }
        if (has_b) {
            const uint32_t kb1 = sb + 12800u * 2;
#pragma unroll
            for (int kk = 0; kk < 12; kk++)
#pragma unroll
                for (int nf2 = 0; nf2 < 4; nf2++) {
                    uint32_t b0, b1, b2, b3;
                    ldsm4(lmaddr(kb1, nf2 * 16, 200, kk * 16, lane), b0, b1, b2, b3);
                    mma16816(Sc[8 + 2 * nf2],     qf[kk][0], qf[kk][1], qf[kk][2], qf[kk][3], b0, b2);
                    mma16816(Sc[8 + 2 * nf2 + 1], qf[kk][0], qf[kk][1], qf[kk][2], qf[kk][3], b1, b3);
                }
        } else {
#pragma unroll
            for (int f = 8; f < 16; f++) {
                Sc[f][0] = MASKVAL; Sc[f][1] = MASKVAL; Sc[f][2] = MASKVAL; Sc[f][3] = MASKVAL;
            }
        }
        // diagonal mask (only the last sub needs it)
        if (s0 == smax) {
#pragma unroll
            for (int f = 0; f < 8; f++) {
                int c0 = smax * 64 + f * 8 + t2 * 2;
                Sc[f][0] = (c0     <= gr0) ? Sc[f][0] : MASKVAL;
                Sc[f][1] = (c0 + 1 <= gr0) ? Sc[f][1] : MASKVAL;
                Sc[f][2] = (c0     <= gr1) ? Sc[f][2] : MASKVAL;
                Sc[f][3] = (c0 + 1 <= gr1) ? Sc[f][3] : MASKVAL;
            }
        } else if (s0 + 1 == smax) {
#pragma unroll
            for (int f = 0; f < 8; f++) {
                int c0 = smax * 64 + f * 8 + t2 * 2;
                Sc[8+f][0] = (c0     <= gr0) ? Sc[8+f][0] : MASKVAL;
                Sc[8+f][1] = (c0 + 1 <= gr0) ? Sc[8+f][1] : MASKVAL;
                Sc[8+f][2] = (c0     <= gr1) ? Sc[8+f][2] : MASKVAL;
                Sc[8+f][3] = (c0 + 1 <= gr1) ? Sc[8+f][3] : MASKVAL;
            }
        }

        // ---- online softmax over 128 keys ----
        float mx0 = -INFINITY, mx1 = -INFINITY;
#pragma unroll
        for (int f = 0; f < 16; f++) {
            mx0 = fmaxf(mx0, fmaxf(Sc[f][0], Sc[f][1]));
            mx1 = fmaxf(mx1, fmaxf(Sc[f][2], Sc[f][3]));
        }
        mx0 = fmaxf(mx0, __shfl_xor_sync(0xffffffffu, mx0, 1));
        mx0 = fmaxf(mx0, __shfl_xor_sync(0xffffffffu, mx0, 2));
        mx1 = fmaxf(mx1, __shfl_xor_sync(0xffffffffu, mx1, 1));
        mx1 = fmaxf(mx1, __shfl_xor_sync(0xffffffffu, mx1, 2));
        float mn0 = fmaxf(mr0, mx0), mn1 = fmaxf(mr1, mx1);
        float al0 = exp2f(mr0 - mn0), al1 = exp2f(mr1 - mn1);
        mr0 = mn0; mr1 = mn1;

        if (!__all_sync(0xffffffffu, (al0 == 1.f) & (al1 == 1.f))) {
#pragma unroll
            for (int f = 0; f < 16; f++) {
                O[f][0] *= al0; O[f][1] *= al0; O[f][2] *= al1; O[f][3] *= al1;
            }
            Osum[0] *= al0; Osum[1] *= al0; Osum[2] *= al1; Osum[3] *= al1;
        }

        uint32_t Pa[16], Pb[16];
#pragma unroll
        for (int f = 0; f < 16; f++) {
            Pa[f] = hexp2(pack2(Sc[f][0] - mn0, Sc[f][1] - mn0));
            Pb[f] = hexp2(pack2(Sc[f][2] - mn1, Sc[f][3] - mn1));
        }

        __syncthreads();                  // K bufs + V buf (s0+2)%3 free
        if (s0 + 2 <= smax) { prefK(s0 + 2); prefV(s0 + 2); }
        if (s0 + 3 <= smax) prefK(s0 + 3);
        CP_COMMIT();

        // ---- PV over both subs ----
        {
            const uint32_t vb = sb + (VBASE + (uint32_t)(s0 % 3) * VSZ) * 2;
#pragma unroll
            for (int kc2 = 0; kc2 < 4; kc2++) {
                uint32_t a0 = Pa[2*kc2], a1 = Pb[2*kc2], a2 = Pa[2*kc2+1], a3 = Pb[2*kc2+1];
#pragma unroll
                for (int nf2 = 0; nf2 < 8; nf2++) {
                    uint32_t b0, b1, b2, b3;
                    ldsm4(lmaddr(vb, nf2 * 16, 72, kc2 * 16, lane), b0, b1, b2, b3);
                    mma16816(O[2 * nf2],     a0, a1, a2, a3, b0, b2);
                    mma16816(O[2 * nf2 + 1], a0, a1, a2, a3, b1, b3);
                }
                uint32_t b0, b1, b2, b3;
                ldsm4(lmaddr(vb, 128, 72, kc2 * 16, lane), b0, b1, b2, b3);
                mma16816(Osum, a0, a1, a2, a3, b0, b2);
            }
        }
        if (has_b) {
            const uint32_t vb = sb + (VBASE + (uint32_t)((s0 + 1) % 3) * VSZ) * 2;
#pragma unroll
            for (int kc2 = 0; kc2 < 4; kc2++) {
                uint32_t a0 = Pa[8+2*kc2], a1 = Pb[8+2*kc2], a2 = Pa[8+2*kc2+1], a3 = Pb[8+2*kc2+1];
#pragma unroll
                for (int nf2 = 0; nf2 < 8; nf2++) {
                    uint32_t b0, b1, b2, b3;
                    ldsm4(lmaddr(vb, nf2 * 16, 72, kc2 * 16, lane), b0, b1, b2, b3);
                    mma16816(O[2 * nf2],     a0, a1, a2, a3, b0, b2);
                    mma16816(O[2 * nf2 + 1], a0, a1, a2, a3, b1, b3);
                }
                uint32_t b0, b1, b2, b3;
                ldsm4(lmaddr(vb, 128, 72, kc2 * 16, lane), b0, b1, b2, b3);
                mma16816(Osum, a0, a1, a2, a3, b0, b2);
            }
        }
        __syncthreads();                  // V bufs s0%3,(s0+1)%3 free
        if (s0 + 3 <= smax) prefV(s0 + 3);
        CP_COMMIT();
    }

    // epilogue
    float sum0 = __shfl_sync(0xffffffffu, Osum[0], lane & ~3);
    float sum1 = __shfl_sync(0xffffffffu, Osum[2], lane & ~3);
    float inv0 = 1.f / sum0, inv1 = 1.f / sum1;
#pragma unroll
    for (int f = 0; f < 16; f++) {
        int col = h * 128 + f * 8 + t2 * 2;
        *(float2*)(out + (size_t)gr0 * 2048 + col) = make_float2(O[f][0] * inv0, O[f][1] * inv0);
        *(float2*)(out + (size_t)gr1 * 2048 + col) = make_float2(O[f][2] * inv1, O[f][3] * inv1);
    }
}

// ---------------------------------------------------------------------------
extern "C" void kernel_launch(void* const* d_in, const int* in_sizes, int n_in,
                              void* d_out, int out_size) {
    (void)in_sizes; (void)n_in; (void)out_size;
    const float* q   = (const float*)d_in[0];
    const float* kc  = (const float*)d_in[1];
    const float* kpe = (const float*)d_in[2];
    const float* wkv = (const float*)d_in[3];
    const float* wuv = (const float*)d_in[4];
    float* out = (float*)d_out;

    conv_w_t <<<dim3(32, 16), 256>>>(wkv, wuv);
    conv_misc<<<4096, 256>>>(kc, kpe);

    cudaFuncSetAttribute(pregemm, cudaFuncAttributeMaxDynamicSharedMemorySize, PG_SMEM);
    cudaFuncSetAttribute(attn,    cudaFuncAttributeMaxDynamicSharedMemorySize, AT_SMEM);

    pregemm<<<dim3(32, 16), 256, PG_SMEM>>>();
    attn<<<dim3(32, 16), 128, AT_SMEM>>>(q, out);
}

// round 13
// speedup vs baseline: 30.2771x; 1.2157x over previous
#include <cuda_runtime.h>
#include <cuda_fp16.h>
#include <math.h>
#include <stdint.h>

#define TSEQ   2048
#define NH     16
#define DLORA  512
// SCALE * log2(e)
#define QS      0.1041277131f
#define MASKVAL (-30000.f)

// ---------------- scratch (device globals; allocation-free) ----------------
__device__ __half g_kc_h[TSEQ * DLORA];          // [t][l]
__device__ __half g_wt_h[4096 * DLORA];          // [n][l] combined weight^T
__device__ __half g_ksp[TSEQ * NH * 192];        // [t][h][ nope(128)|rope(64) ]
__device__ __half g_vt[NH * 128 * TSEQ];         // [h][dv][t]
__device__ int    g_job;                         // attn work-queue counter

// ---------------- helpers ----------------
__device__ __forceinline__ uint32_t smem_u32(const void* p) {
    uint32_t a;
    asm("{ .reg .u64 t; cvta.to.shared.u64 t, %1; cvt.u32.u64 %0, t; }" : "=r"(a) : "l"(p));
    return a;
}
__device__ __forceinline__ uint32_t pack2(float a, float b) {
    __half2 h = __floats2half2_rn(a, b);
    return *reinterpret_cast<uint32_t*>(&h);
}
__device__ __forceinline__ uint32_t hexp2(uint32_t h) {
    uint32_t r;
    asm("ex2.approx.f16x2 %0, %1;" : "=r"(r) : "r"(h));
    return r;
}
__device__ __forceinline__ void ldsm4(uint32_t a, uint32_t& r0, uint32_t& r1, uint32_t& r2, uint32_t& r3) {
    asm volatile("ldmatrix.sync.aligned.m8n8.x4.shared.b16 {%0,%1,%2,%3}, [%4];"
                 : "=r"(r0), "=r"(r1), "=r"(r2), "=r"(r3) : "r"(a));
}
__device__ __forceinline__ void mma16816(float* c, uint32_t a0, uint32_t a1, uint32_t a2, uint32_t a3,
                                         uint32_t b0, uint32_t b1) {
    asm volatile("mma.sync.aligned.m16n8k16.row.col.f32.f16.f16.f32 "
                 "{%0,%1,%2,%3}, {%4,%5,%6,%7}, {%8,%9}, {%0,%1,%2,%3};"
                 : "+f"(c[0]), "+f"(c[1]), "+f"(c[2]), "+f"(c[3])
                 : "r"(a0), "r"(a1), "r"(a2), "r"(a3), "r"(b0), "r"(b1));
}
__device__ __forceinline__ uint32_t lmaddr(uint32_t base, int row0, int pitch, int col0, int lane) {
    return base + (uint32_t)(((row0 + (lane & 15)) * pitch + col0 + ((lane >> 4) << 3)) * 2);
}
__device__ __forceinline__ void cp16(uint32_t d, const void* s) {
    asm volatile("cp.async.cg.shared.global [%0], [%1], 16;" :: "r"(d), "l"(s));
}
#define CP_COMMIT() asm volatile("cp.async.commit_group;" ::: "memory")
#define CP_WAIT0()  asm volatile("cp.async.wait_group 0;" ::: "memory")
#define CP_WAIT1()  asm volatile("cp.async.wait_group 1;" ::: "memory")

// ---------------- converters ----------------
__global__ __launch_bounds__(256) void conv_w_t(const float* __restrict__ wkv,
                                                const float* __restrict__ wuv) {
    __shared__ __half sW[32][130];
    const int nt = blockIdx.x;   // 0..31 -> n tile of 128
    const int lt = blockIdx.y;   // 0..15 -> l tile of 32
    const int tid = threadIdx.x;
    const bool isW = nt < 16;
#pragma unroll
    for (int it = 0; it < 16; it++) {
        int idx = tid + it * 256;
        int nl = idx & 127, ll = idx >> 7;
        int l = lt * 32 + ll;
        float x;
        if (isW) x = wkv[(size_t)l * 4096 + nt * 256 + nl];
        else     x = wuv[(size_t)(nt - 16) * 65536 + (size_t)l * 128 + nl];
        sW[ll][nl] = __float2half_rn(x);
    }
    __syncthreads();
    int ll = tid & 31;
    int n0 = (tid >> 5) * 16;
#pragma unroll
    for (int i = 0; i < 16; i++) {
        int n = n0 + i;
        g_wt_h[(size_t)(nt * 128 + n) * 512 + lt * 32 + ll] = sW[ll][n];
    }
}
// kc (vectorized) + rope broadcast + queue reset
__global__ void conv_misc(const float* __restrict__ kc, const float* __restrict__ kpe) {
    int i = blockIdx.x * blockDim.x + threadIdx.x;
    if (i == 0) g_job = 0;
    if (i < TSEQ * DLORA / 4) {
        float4 v = *(const float4*)(kc + (size_t)i * 4);
        *(uint2*)(g_kc_h + (size_t)i * 4) = make_uint2(pack2(v.x, v.y), pack2(v.z, v.w));
    }
    {
        int t = i >> 9, h = (i >> 5) & 15, d2 = i & 31;
        float2 v = *(const float2*)(kpe + t * 64 + d2 * 2);
        *(uint32_t*)(g_ksp + (size_t)(t * 16 + h) * 192 + 128 + d2 * 2) = pack2(v.x, v.y);
    }
}

// ---------------- pre-GEMM: D = kc_hi @ W_hi^T, single-stage, 2 CTA/SM ----------
#define PG_SMEM 69632
__global__ __launch_bounds__(256, 2) void pregemm() {
    extern __shared__ __align__(16) __half smh[];
    float* sT = (float*)smh;
    const uint32_t sb = smem_u32(smh);
    const uint32_t Ab = sb, Bb = sb + 17408u * 2;
    const int nt = blockIdx.x, mt = blockIdx.y;
    const int tid = threadIdx.x, lane = tid & 31, w = tid >> 5;
    const int wm = w >> 2, wn = w & 3;
    const int g = lane >> 2, t2 = lane & 3;

    float acc[4][4][4];
#pragma unroll
    for (int a = 0; a < 4; a++)
#pragma unroll
        for (int b = 0; b < 4; b++)
#pragma unroll
            for (int c = 0; c < 4; c++) acc[a][b][c] = 0.f;

    for (int chunk = 0; chunk < 4; chunk++) {
        const int kk = chunk * 128;
#pragma unroll
        for (int it = 0; it < 8; it++) {
            int idx = tid + it * 256;
            int r = idx >> 4, c = idx & 15;
            uint32_t off = (uint32_t)(r * 136 + c * 8) * 2;
            cp16(Ab + off, g_kc_h + (size_t)(mt * 128 + r) * 512 + kk + c * 8);
            cp16(Bb + off, g_wt_h + (size_t)(nt * 128 + r) * 512 + kk + c * 8);
        }
        CP_COMMIT();
        CP_WAIT0();
        __syncthreads();
#pragma unroll
        for (int ks = 0; ks < 8; ks++) {
            uint32_t af[4][4];
#pragma unroll
            for (int mf = 0; mf < 4; mf++)
                ldsm4(lmaddr(Ab, wm * 64 + mf * 16, 136, ks * 16, lane),
                      af[mf][0], af[mf][1], af[mf][2], af[mf][3]);
#pragma unroll
            for (int ng = 0; ng < 2; ng++) {
                uint32_t b0, b1, b2, b3;
                ldsm4(lmaddr(Bb, wn * 32 + ng * 16, 136, ks * 16, lane), b0, b1, b2, b3);
#pragma unroll
                for (int mf = 0; mf < 4; mf++) {
                    mma16816(acc[mf][2 * ng],     af[mf][0], af[mf][1], af[mf][2], af[mf][3], b0, b2);
                    mma16816(acc[mf][2 * ng + 1], af[mf][0], af[mf][1], af[mf][2], af[mf][3], b1, b3);
                }
            }
        }
        __syncthreads();
    }

#pragma unroll
    for (int mf = 0; mf < 4; mf++)
#pragma unroll
        for (int nf = 0; nf < 4; nf++) {
            int rr = wm * 64 + mf * 16 + g, cc = wn * 32 + nf * 8 + 2 * t2;
            sT[rr * 129 + cc]       = acc[mf][nf][0];
            sT[rr * 129 + cc + 1]   = acc[mf][nf][1];
            sT[(rr + 8) * 129 + cc]     = acc[mf][nf][2];
            sT[(rr + 8) * 129 + cc + 1] = acc[mf][nf][3];
        }
    __syncthreads();

    if (tid < 128) {
        if (nt < 16) {
            size_t base = (size_t)((mt * 128 + tid) * 16 + nt) * 192;
#pragma unroll
            for (int ch = 0; ch < 4; ch++) {
                uint32_t hh[16];
#pragma unroll
                for (int i = 0; i < 16; i++)
                    hh[i] = pack2(sT[tid * 129 + ch * 32 + 2 * i], sT[tid * 129 + ch * 32 + 2 * i + 1]);
#pragma unroll
                for (int k = 0; k < 4; k++)
                    *(uint4*)(g_ksp + base + ch * 32 + k * 8) = make_uint4(hh[4*k], hh[4*k+1], hh[4*k+2], hh[4*k+3]);
            }
        } else {
            int h = nt - 16;
            size_t base = (size_t)(h * 128 + tid) * 2048 + mt * 128;
#pragma unroll
            for (int ch = 0; ch < 4; ch++) {
                uint32_t hh[16];
#pragma unroll
                for (int i = 0; i < 16; i++)
                    hh[i] = pack2(sT[(ch * 32 + 2 * i) * 129 + tid], sT[(ch * 32 + 2 * i + 1) * 129 + tid]);
#pragma unroll
                for (int k = 0; k < 4; k++)
                    *(uint4*)(g_vt + base + ch * 32 + k * 8) = make_uint4(hh[4*k], hh[4*k+1], hh[4*k+2], hh[4*k+3]);
            }
        }
    }
}

// ---------------- attention: persistent work-queue, 64-key tiles, 2 CTA/SM -----
// smem (halfs): K0:0 (64x200) | K1:12800 | V0:25600 (144x72) | V1:35968 = 92672 B
#define AT_SMEM 92672
#define NJOBS   512
__global__ __launch_bounds__(128, 2) void attn(const float* __restrict__ q, float* __restrict__ out) {
    extern __shared__ __align__(16) __half smh[];
    __shared__ int s_job;
    const uint32_t sb = smem_u32(smh);
    const int tid = threadIdx.x, lane = tid & 31, w = tid >> 5;
    const int m0 = w * 16, g = lane >> 2, t2 = lane & 3;

    // ones rows (128..135) of both V buffers (persist across jobs)
    for (int idx = tid; idx < 2 * 8 * 72; idx += 128) {
        int b = idx / (8 * 72), rem = idx % (8 * 72);
        int r = rem / 72, c = rem % 72;
        smh[25600 + b * 10368 + (128 + r) * 72 + c] =
            (r == 0 && c < 64) ? __float2half(1.f) : __float2half(0.f);
    }

    for (;;) {
        if (tid == 0) s_job = atomicAdd(&g_job, 1);
        __syncthreads();
        const int job = s_job;
        if (job >= NJOBS) break;
        // LPT order: big qt first
        const int qt = 31 - (job >> 4), h = job & 15;
        const int gr0 = qt * 64 + m0 + g, gr1 = gr0 + 8;
        const int jmax = qt;

        // stage Q into K0 buffer (prescaled), hoist frags
        for (int idx = tid; idx < 64 * 48; idx += 128) {
            int r = idx / 48, c = idx % 48;
            float4 v = *(const float4*)(q + (size_t)((qt * 64 + r) * 16 + h) * 192 + c * 4);
            *(uint2*)(smh + r * 200 + c * 4) =
                make_uint2(pack2(v.x * QS, v.y * QS), pack2(v.z * QS, v.w * QS));
        }
        __syncthreads();
        uint32_t qf[12][4];
#pragma unroll
        for (int kk = 0; kk < 12; kk++)
            ldsm4(lmaddr(sb, m0, 200, kk * 16, lane), qf[kk][0], qf[kk][1], qf[kk][2], qf[kk][3]);
        __syncthreads();

        auto prefetch = [&](int j, int buf) {
            uint32_t kb = sb + (uint32_t)buf * 12800u * 2;
            uint32_t vb = sb + (25600u + (uint32_t)buf * 10368u) * 2;
#pragma unroll
            for (int it = 0; it < 12; it++) {
                int idx = tid + it * 128;
                int r = idx / 24, c = idx % 24;
                cp16(kb + (uint32_t)(r * 200 + c * 8) * 2,
                     g_ksp + (size_t)((j * 64 + r) * 16 + h) * 192 + c * 8);
            }
#pragma unroll
            for (int it = 0; it < 8; it++) {
                int idx = tid + it * 128;
                int r = idx >> 3, c = idx & 7;
                cp16(vb + (uint32_t)(r * 72 + c * 8) * 2,
                     g_vt + (size_t)(h * 128 + r) * 2048 + j * 64 + c * 8);
            }
        };

        prefetch(0, 0); CP_COMMIT();

        float O[16][4], Osum[4];
#pragma unroll
        for (int f = 0; f < 16; f++)
#pragma unroll
            for (int c = 0; c < 4; c++) O[f][c] = 0.f;
#pragma unroll
        for (int c = 0; c < 4; c++) Osum[c] = 0.f;
        float mr0 = -INFINITY, mr1 = -INFINITY;

        for (int j = 0; j <= jmax; j++) {
            if (j < jmax) { prefetch(j + 1, (j + 1) & 1); CP_COMMIT(); CP_WAIT1(); }
            else         { CP_WAIT0(); }
            __syncthreads();
            const uint32_t sKb = sb + (uint32_t)(j & 1) * 12800u * 2;
            const uint32_t sVb = sb + (25600u + (uint32_t)(j & 1) * 10368u) * 2;

            // S = Q @ K^T
            float Sc[8][4];
#pragma unroll
            for (int f = 0; f < 8; f++)
#pragma unroll
                for (int c = 0; c < 4; c++) Sc[f][c] = 0.f;
#pragma unroll
            for (int kk = 0; kk < 12; kk++) {
#pragma unroll
                for (int nf2 = 0; nf2 < 4; nf2++) {
                    uint32_t b0, b1, b2, b3;
                    ldsm4(lmaddr(sKb, nf2 * 16, 200, kk * 16, lane), b0, b1, b2, b3);
                    mma16816(Sc[2 * nf2],     qf[kk][0], qf[kk][1], qf[kk][2], qf[kk][3], b0, b2);
                    mma16816(Sc[2 * nf2 + 1], qf[kk][0], qf[kk][1], qf[kk][2], qf[kk][3], b1, b3);
                }
            }

            // mask only on diagonal tile
            if (j == jmax) {
#pragma unroll
                for (int f = 0; f < 8; f++) {
                    int c0 = j * 64 + f * 8 + t2 * 2;
                    Sc[f][0] = (c0     <= gr0) ? Sc[f][0] : MASKVAL;
                    Sc[f][1] = (c0 + 1 <= gr0) ? Sc[f][1] : MASKVAL;
                    Sc[f][2] = (c0     <= gr1) ? Sc[f][2] : MASKVAL;
                    Sc[f][3] = (c0 + 1 <= gr1) ? Sc[f][3] : MASKVAL;
                }
            }
            // row max
            float mx0 = -INFINITY, mx1 = -INFINITY;
#pragma unroll
            for (int f = 0; f < 8; f++) {
                mx0 = fmaxf(mx0, fmaxf(Sc[f][0], Sc[f][1]));
                mx1 = fmaxf(mx1, fmaxf(Sc[f][2], Sc[f][3]));
            }
            mx0 = fmaxf(mx0, __shfl_xor_sync(0xffffffffu, mx0, 1));
            mx0 = fmaxf(mx0, __shfl_xor_sync(0xffffffffu, mx0, 2));
            mx1 = fmaxf(mx1, __shfl_xor_sync(0xffffffffu, mx1, 1));
            mx1 = fmaxf(mx1, __shfl_xor_sync(0xffffffffu, mx1, 2));
            float mn0 = fmaxf(mr0, mx0), mn1 = fmaxf(mr1, mx1);
            float al0 = exp2f(mr0 - mn0), al1 = exp2f(mr1 - mn1);
            mr0 = mn0; mr1 = mn1;

            if (!__all_sync(0xffffffffu, (al0 == 1.f) & (al1 == 1.f))) {
#pragma unroll
                for (int f = 0; f < 16; f++) {
                    O[f][0] *= al0; O[f][1] *= al0; O[f][2] *= al1; O[f][3] *= al1;
                }
                Osum[0] *= al0; Osum[1] *= al0; Osum[2] *= al1; Osum[3] *= al1;
            }

            uint32_t Pa[8], Pb[8];
#pragma unroll
            for (int f = 0; f < 8; f++) {
                Pa[f] = hexp2(pack2(Sc[f][0] - mn0, Sc[f][1] - mn0));
                Pb[f] = hexp2(pack2(Sc[f][2] - mn1, Sc[f][3] - mn1));
            }

            // O += P @ V  (and row-sum via ones row)
#pragma unroll
            for (int kc2 = 0; kc2 < 4; kc2++) {
                uint32_t a0 = Pa[2 * kc2], a1 = Pb[2 * kc2], a2 = Pa[2 * kc2 + 1], a3 = Pb[2 * kc2 + 1];
#pragma unroll
                for (int nf2 = 0; nf2 < 8; nf2++) {
                    uint32_t b0, b1, b2, b3;
                    ldsm4(lmaddr(sVb, nf2 * 16, 72, kc2 * 16, lane), b0, b1, b2, b3);
                    mma16816(O[2 * nf2],     a0, a1, a2, a3, b0, b2);
                    mma16816(O[2 * nf2 + 1], a0, a1, a2, a3, b1, b3);
                }
                uint32_t b0, b1, b2, b3;
                ldsm4(lmaddr(sVb, 128, 72, kc2 * 16, lane), b0, b1, b2, b3);
                mma16816(Osum, a0, a1, a2, a3, b0, b2);
            }
            __syncthreads();
        }

        // epilogue
        float sum0 = __shfl_sync(0xffffffffu, Osum[0], lane & ~3);
        float sum1 = __shfl_sync(0xffffffffu, Osum[2], lane & ~3);
        float inv0 = 1.f / sum0, inv1 = 1.f / sum1;
#pragma unroll
        for (int f = 0; f < 16; f++) {
            int col = h * 128 + f * 8 + t2 * 2;
            *(float2*)(out + (size_t)gr0 * 2048 + col) = make_float2(O[f][0] * inv0, O[f][1] * inv0);
            *(float2*)(out + (size_t)gr1 * 2048 + col) = make_float2(O[f][2] * inv1, O[f][3] * inv1);
        }
        __syncthreads();
    }
}

// ---------------------------------------------------------------------------
extern "C" void kernel_launch(void* const* d_in, const int* in_sizes, int n_in,
                              void* d_out, int out_size) {
    (void)in_sizes; (void)n_in; (void)out_size;
    const float* q   = (const float*)d_in[0];
    const float* kc  = (const float*)d_in[1];
    const float* kpe = (const float*)d_in[2];
    const float* wkv = (const float*)d_in[3];
    const float* wuv = (const float*)d_in[4];
    float* out = (float*)d_out;

    conv_w_t <<<dim3(32, 16), 256>>>(wkv, wuv);
    conv_misc<<<4096, 256>>>(kc, kpe);

    cudaFuncSetAttribute(pregemm, cudaFuncAttributeMaxDynamicSharedMemorySize, PG_SMEM);
    cudaFuncSetAttribute(attn,    cudaFuncAttributeMaxDynamicSharedMemorySize, AT_SMEM);

    pregemm<<<dim3(32, 16), 256, PG_SMEM>>>();
    attn<<<296, 128, AT_SMEM>>>(q, out);
}

// round 14
// speedup vs baseline: 30.8336x; 1.0184x over previous
#include <cuda_runtime.h>
#include <cuda_fp16.h>
#include <math.h>
#include <stdint.h>

#define TSEQ   2048
#define NH     16
#define DLORA  512
// SCALE * log2(e)
#define QS      0.1041277131f
#define MASKVAL (-30000.f)

// ---------------- scratch (device globals; allocation-free) ----------------
__device__ __half g_kc_h[TSEQ * DLORA];          // [t][l]
__device__ __half g_wt_h[4096 * DLORA];          // [n][l] combined weight^T
__device__ __half g_ksp[TSEQ * NH * 192];        // [t][h][ nope(128)|rope(64) ]
__device__ __half g_vt[NH * 128 * TSEQ];         // [h][dv][t]
__device__ int    g_job;                         // attn work-queue counter

// ---------------- helpers ----------------
__device__ __forceinline__ uint32_t smem_u32(const void* p) {
    uint32_t a;
    asm("{ .reg .u64 t; cvta.to.shared.u64 t, %1; cvt.u32.u64 %0, t; }" : "=r"(a) : "l"(p));
    return a;
}
__device__ __forceinline__ uint32_t pack2(float a, float b) {
    __half2 h = __floats2half2_rn(a, b);
    return *reinterpret_cast<uint32_t*>(&h);
}
__device__ __forceinline__ uint32_t hexp2(uint32_t h) {
    uint32_t r;
    asm("ex2.approx.f16x2 %0, %1;" : "=r"(r) : "r"(h));
    return r;
}
__device__ __forceinline__ void ldsm4(uint32_t a, uint32_t& r0, uint32_t& r1, uint32_t& r2, uint32_t& r3) {
    asm volatile("ldmatrix.sync.aligned.m8n8.x4.shared.b16 {%0,%1,%2,%3}, [%4];"
                 : "=r"(r0), "=r"(r1), "=r"(r2), "=r"(r3) : "r"(a));
}
__device__ __forceinline__ void mma16816(float* c, uint32_t a0, uint32_t a1, uint32_t a2, uint32_t a3,
                                         uint32_t b0, uint32_t b1) {
    asm volatile("mma.sync.aligned.m16n8k16.row.col.f32.f16.f16.f32 "
                 "{%0,%1,%2,%3}, {%4,%5,%6,%7}, {%8,%9}, {%0,%1,%2,%3};"
                 : "+f"(c[0]), "+f"(c[1]), "+f"(c[2]), "+f"(c[3])
                 : "r"(a0), "r"(a1), "r"(a2), "r"(a3), "r"(b0), "r"(b1));
}
__device__ __forceinline__ uint32_t lmaddr(uint32_t base, int row0, int pitch, int col0, int lane) {
    return base + (uint32_t)(((row0 + (lane & 15)) * pitch + col0 + ((lane >> 4) << 3)) * 2);
}
__device__ __forceinline__ void cp16(uint32_t d, const void* s) {
    asm volatile("cp.async.cg.shared.global [%0], [%1], 16;" :: "r"(d), "l"(s));
}
#define CP_COMMIT() asm volatile("cp.async.commit_group;" ::: "memory")
#define CP_WAIT0()  asm volatile("cp.async.wait_group 0;" ::: "memory")
#define CP_WAIT1()  asm volatile("cp.async.wait_group 1;" ::: "memory")

// ---------------- fused converter (one launch) ----------------
// blocks [0,512): W transpose tiles; blocks [512, 4608): kc + rope + queue reset
__global__ __launch_bounds__(256) void conv_all(const float* __restrict__ wkv,
                                                const float* __restrict__ wuv,
                                                const float* __restrict__ kc,
                                                const float* __restrict__ kpe) {
    const int bid = blockIdx.x, tid = threadIdx.x;
    if (bid < 512) {
        __shared__ __half sW[32][130];
        const int nt = bid & 31;   // n tile of 128
        const int lt = bid >> 5;   // l tile of 32
        const bool isW = nt < 16;
#pragma unroll
        for (int it = 0; it < 16; it++) {
            int idx = tid + it * 256;
            int nl = idx & 127, ll = idx >> 7;
            int l = lt * 32 + ll;
            float x;
            if (isW) x = wkv[(size_t)l * 4096 + nt * 256 + nl];
            else     x = wuv[(size_t)(nt - 16) * 65536 + (size_t)l * 128 + nl];
            sW[ll][nl] = __float2half_rn(x);
        }
        __syncthreads();
        int ll = tid & 31;
        int n0 = (tid >> 5) * 16;
#pragma unroll
        for (int i = 0; i < 16; i++) {
            int n = n0 + i;
            g_wt_h[(size_t)(nt * 128 + n) * 512 + lt * 32 + ll] = sW[ll][n];
        }
    } else {
        int i = (bid - 512) * 256 + tid;
        if (i == 0) g_job = 0;
        if (i < TSEQ * DLORA / 4) {
            float4 v = *(const float4*)(kc + (size_t)i * 4);
            *(uint2*)(g_kc_h + (size_t)i * 4) = make_uint2(pack2(v.x, v.y), pack2(v.z, v.w));
        }
        {
            int t = i >> 9, h = (i >> 5) & 15, d2 = i & 31;
            float2 v = *(const float2*)(kpe + t * 64 + d2 * 2);
            *(uint32_t*)(g_ksp + (size_t)(t * 16 + h) * 192 + 128 + d2 * 2) = pack2(v.x, v.y);
        }
    }
}

// ---------------- pre-GEMM: D = kc_hi @ W_hi^T, k=64 chunks double-buffered -------
// smem halves: A0:0 (128x72) | B0:9216 | A1:18432 | B1:27648  = 73728 B
// fp32 staging sT [128][129] (66048 B) aliases the buffers after the mainloop.
#define PG_SMEM 73728
__global__ __launch_bounds__(256, 2) void pregemm() {
    extern __shared__ __align__(16) __half smh[];
    float* sT = (float*)smh;
    const uint32_t sb = smem_u32(smh);
    const int nt = blockIdx.x, mt = blockIdx.y;
    const int tid = threadIdx.x, lane = tid & 31, w = tid >> 5;
    const int wm = w >> 2, wn = w & 3;
    const int g = lane >> 2, t2 = lane & 3;

    float acc[4][4][4];
#pragma unroll
    for (int a = 0; a < 4; a++)
#pragma unroll
        for (int b = 0; b < 4; b++)
#pragma unroll
            for (int c = 0; c < 4; c++) acc[a][b][c] = 0.f;

    auto prefetch = [&](int chunk, int buf) {
        const int kk = chunk * 64;
        uint32_t ab = sb + (uint32_t)buf * 18432u * 2;
        uint32_t bb = ab + 9216u * 2;
#pragma unroll
        for (int it = 0; it < 4; it++) {
            int idx = tid + it * 256;
            int r = idx >> 3, c8 = idx & 7;
            uint32_t off = (uint32_t)(r * 72 + c8 * 8) * 2;
            cp16(ab + off, g_kc_h + (size_t)(mt * 128 + r) * 512 + kk + c8 * 8);
            cp16(bb + off, g_wt_h + (size_t)(nt * 128 + r) * 512 + kk + c8 * 8);
        }
    };

    prefetch(0, 0); CP_COMMIT();
    for (int chunk = 0; chunk < 8; chunk++) {
        if (chunk < 7) { prefetch(chunk + 1, (chunk + 1) & 1); CP_COMMIT(); CP_WAIT1(); }
        else           { CP_WAIT0(); }
        __syncthreads();
        uint32_t ab = sb + (uint32_t)(chunk & 1) * 18432u * 2;
        uint32_t bb = ab + 9216u * 2;
#pragma unroll
        for (int ks = 0; ks < 4; ks++) {
            uint32_t af[4][4];
#pragma unroll
            for (int mf = 0; mf < 4; mf++)
                ldsm4(lmaddr(ab, wm * 64 + mf * 16, 72, ks * 16, lane),
                      af[mf][0], af[mf][1], af[mf][2], af[mf][3]);
#pragma unroll
            for (int ng = 0; ng < 2; ng++) {
                uint32_t b0, b1, b2, b3;
                ldsm4(lmaddr(bb, wn * 32 + ng * 16, 72, ks * 16, lane), b0, b1, b2, b3);
#pragma unroll
                for (int mf = 0; mf < 4; mf++) {
                    mma16816(acc[mf][2 * ng],     af[mf][0], af[mf][1], af[mf][2], af[mf][3], b0, b2);
                    mma16816(acc[mf][2 * ng + 1], af[mf][0], af[mf][1], af[mf][2], af[mf][3], b1, b3);
                }
            }
        }
        __syncthreads();   // all reads of this buffer done before it is refilled
    }

    // stage accumulators to sT [row][col] pitch 129 (aliases buffers; mainloop done)
#pragma unroll
    for (int mf = 0; mf < 4; mf++)
#pragma unroll
        for (int nf = 0; nf < 4; nf++) {
            int rr = wm * 64 + mf * 16 + g, cc = wn * 32 + nf * 8 + 2 * t2;
            sT[rr * 129 + cc]       = acc[mf][nf][0];
            sT[rr * 129 + cc + 1]   = acc[mf][nf][1];
            sT[(rr + 8) * 129 + cc]     = acc[mf][nf][2];
            sT[(rr + 8) * 129 + cc + 1] = acc[mf][nf][3];
        }
    __syncthreads();

    if (tid < 128) {
        if (nt < 16) {
            size_t base = (size_t)((mt * 128 + tid) * 16 + nt) * 192;
#pragma unroll
            for (int ch = 0; ch < 4; ch++) {
                uint32_t hh[16];
#pragma unroll
                for (int i = 0; i < 16; i++)
                    hh[i] = pack2(sT[tid * 129 + ch * 32 + 2 * i], sT[tid * 129 + ch * 32 + 2 * i + 1]);
#pragma unroll
                for (int k = 0; k < 4; k++)
                    *(uint4*)(g_ksp + base + ch * 32 + k * 8) = make_uint4(hh[4*k], hh[4*k+1], hh[4*k+2], hh[4*k+3]);
            }
        } else {
            int h = nt - 16;
            size_t base = (size_t)(h * 128 + tid) * 2048 + mt * 128;
#pragma unroll
            for (int ch = 0; ch < 4; ch++) {
                uint32_t hh[16];
#pragma unroll
                for (int i = 0; i < 16; i++)
                    hh[i] = pack2(sT[(ch * 32 + 2 * i) * 129 + tid], sT[(ch * 32 + 2 * i + 1) * 129 + tid]);
#pragma unroll
                for (int k = 0; k < 4; k++)
                    *(uint4*)(g_vt + base + ch * 32 + k * 8) = make_uint4(hh[4*k], hh[4*k+1], hh[4*k+2], hh[4*k+3]);
            }
        }
    }
}

// ---------------- attention: persistent work-queue, 64-key tiles, 2 CTA/SM -----
// smem (halfs): K0:0 (64x200) | K1:12800 | V0:25600 (144x72) | V1:35968 = 92672 B
#define AT_SMEM 92672
#define NJOBS   512
__global__ __launch_bounds__(128, 2) void attn(const float* __restrict__ q, float* __restrict__ out) {
    extern __shared__ __align__(16) __half smh[];
    __shared__ int s_job;
    const uint32_t sb = smem_u32(smh);
    const int tid = threadIdx.x, lane = tid & 31, w = tid >> 5;
    const int m0 = w * 16, g = lane >> 2, t2 = lane & 3;

    // ones rows (128..135) of both V buffers (persist across jobs)
    for (int idx = tid; idx < 2 * 8 * 72; idx += 128) {
        int b = idx / (8 * 72), rem = idx % (8 * 72);
        int r = rem / 72, c = rem % 72;
        smh[25600 + b * 10368 + (128 + r) * 72 + c] =
            (r == 0 && c < 64) ? __float2half(1.f) : __float2half(0.f);
    }

    for (;;) {
        if (tid == 0) s_job = atomicAdd(&g_job, 1);
        __syncthreads();
        const int job = s_job;
        if (job >= NJOBS) break;
        // LPT order: big qt first
        const int qt = 31 - (job >> 4), h = job & 15;
        const int gr0 = qt * 64 + m0 + g, gr1 = gr0 + 8;
        const int jmax = qt;

        // stage Q into K0 buffer (prescaled), hoist frags
        for (int idx = tid; idx < 64 * 48; idx += 128) {
            int r = idx / 48, c = idx % 48;
            float4 v = *(const float4*)(q + (size_t)((qt * 64 + r) * 16 + h) * 192 + c * 4);
            *(uint2*)(smh + r * 200 + c * 4) =
                make_uint2(pack2(v.x * QS, v.y * QS), pack2(v.z * QS, v.w * QS));
        }
        __syncthreads();
        uint32_t qf[12][4];
#pragma unroll
        for (int kk = 0; kk < 12; kk++)
            ldsm4(lmaddr(sb, m0, 200, kk * 16, lane), qf[kk][0], qf[kk][1], qf[kk][2], qf[kk][3]);
        __syncthreads();

        auto prefetch = [&](int j, int buf) {
            uint32_t kb = sb + (uint32_t)buf * 12800u * 2;
            uint32_t vb = sb + (25600u + (uint32_t)buf * 10368u) * 2;
#pragma unroll
            for (int it = 0; it < 12; it++) {
                int idx = tid + it * 128;
                int r = idx / 24, c = idx % 24;
                cp16(kb + (uint32_t)(r * 200 + c * 8) * 2,
                     g_ksp + (size_t)((j * 64 + r) * 16 + h) * 192 + c * 8);
            }
#pragma unroll
            for (int it = 0; it < 8; it++) {
                int idx = tid + it * 128;
                int r = idx >> 3, c = idx & 7;
                cp16(vb + (uint32_t)(r * 72 + c * 8) * 2,
                     g_vt + (size_t)(h * 128 + r) * 2048 + j * 64 + c * 8);
            }
        };

        prefetch(0, 0); CP_COMMIT();

        float O[16][4], Osum[4];
#pragma unroll
        for (int f = 0; f < 16; f++)
#pragma unroll
            for (int c = 0; c < 4; c++) O[f][c] = 0.f;
#pragma unroll
        for (int c = 0; c < 4; c++) Osum[c] = 0.f;
        float mr0 = -INFINITY, mr1 = -INFINITY;

        for (int j = 0; j <= jmax; j++) {
            if (j < jmax) { prefetch(j + 1, (j + 1) & 1); CP_COMMIT(); CP_WAIT1(); }
            else         { CP_WAIT0(); }
            __syncthreads();
            const uint32_t sKb = sb + (uint32_t)(j & 1) * 12800u * 2;
            const uint32_t sVb = sb + (25600u + (uint32_t)(j & 1) * 10368u) * 2;

            // S = Q @ K^T
            float Sc[8][4];
#pragma unroll
            for (int f = 0; f < 8; f++)
#pragma unroll
                for (int c = 0; c < 4; c++) Sc[f][c] = 0.f;
#pragma unroll
            for (int kk = 0; kk < 12; kk++) {
#pragma unroll
                for (int nf2 = 0; nf2 < 4; nf2++) {
                    uint32_t b0, b1, b2, b3;
                    ldsm4(lmaddr(sKb, nf2 * 16, 200, kk * 16, lane), b0, b1, b2, b3);
                    mma16816(Sc[2 * nf2],     qf[kk][0], qf[kk][1], qf[kk][2], qf[kk][3], b0, b2);
                    mma16816(Sc[2 * nf2 + 1], qf[kk][0], qf[kk][1], qf[kk][2], qf[kk][3], b1, b3);
                }
            }

            // mask only on diagonal tile
            if (j == jmax) {
#pragma unroll
                for (int f = 0; f < 8; f++) {
                    int c0 = j * 64 + f * 8 + t2 * 2;
                    Sc[f][0] = (c0     <= gr0) ? Sc[f][0] : MASKVAL;
                    Sc[f][1] = (c0 + 1 <= gr0) ? Sc[f][1] : MASKVAL;
                    Sc[f][2] = (c0     <= gr1) ? Sc[f][2] : MASKVAL;
                    Sc[f][3] = (c0 + 1 <= gr1) ? Sc[f][3] : MASKVAL;
                }
            }
            // row max
            float mx0 = -INFINITY, mx1 = -INFINITY;
#pragma unroll
            for (int f = 0; f < 8; f++) {
                mx0 = fmaxf(mx0, fmaxf(Sc[f][0], Sc[f][1]));
                mx1 = fmaxf(mx1, fmaxf(Sc[f][2], Sc[f][3]));
            }
            mx0 = fmaxf(mx0, __shfl_xor_sync(0xffffffffu, mx0, 1));
            mx0 = fmaxf(mx0, __shfl_xor_sync(0xffffffffu, mx0, 2));
            mx1 = fmaxf(mx1, __shfl_xor_sync(0xffffffffu, mx1, 1));
            mx1 = fmaxf(mx1, __shfl_xor_sync(0xffffffffu, mx1, 2));
            float mn0 = fmaxf(mr0, mx0), mn1 = fmaxf(mr1, mx1);
            float al0 = exp2f(mr0 - mn0), al1 = exp2f(mr1 - mn1);
            mr0 = mn0; mr1 = mn1;

            if (!__all_sync(0xffffffffu, (al0 == 1.f) & (al1 == 1.f))) {
#pragma unroll
                for (int f = 0; f < 16; f++) {
                    O[f][0] *= al0; O[f][1] *= al0; O[f][2] *= al1; O[f][3] *= al1;
                }
                Osum[0] *= al0; Osum[1] *= al0; Osum[2] *= al1; Osum[3] *= al1;
            }

            uint32_t Pa[8], Pb[8];
#pragma unroll
            for (int f = 0; f < 8; f++) {
                Pa[f] = hexp2(pack2(Sc[f][0] - mn0, Sc[f][1] - mn0));
                Pb[f] = hexp2(pack2(Sc[f][2] - mn1, Sc[f][3] - mn1));
            }

            // O += P @ V  (and row-sum via ones row)
#pragma unroll
            for (int kc2 = 0; kc2 < 4; kc2++) {
                uint32_t a0 = Pa[2 * kc2], a1 = Pb[2 * kc2], a2 = Pa[2 * kc2 + 1], a3 = Pb[2 * kc2 + 1];
#pragma unroll
                for (int nf2 = 0; nf2 < 8; nf2++) {
                    uint32_t b0, b1, b2, b3;
                    ldsm4(lmaddr(sVb, nf2 * 16, 72, kc2 * 16, lane), b0, b1, b2, b3);
                    mma16816(O[2 * nf2],     a0, a1, a2, a3, b0, b2);
                    mma16816(O[2 * nf2 + 1], a0, a1, a2, a3, b1, b3);
                }
                uint32_t b0, b1, b2, b3;
                ldsm4(lmaddr(sVb, 128, 72, kc2 * 16, lane), b0, b1, b2, b3);
                mma16816(Osum, a0, a1, a2, a3, b0, b2);
            }
            __syncthreads();
        }

        // epilogue
        float sum0 = __shfl_sync(0xffffffffu, Osum[0], lane & ~3);
        float sum1 = __shfl_sync(0xffffffffu, Osum[2], lane & ~3);
        float inv0 = 1.f / sum0, inv1 = 1.f / sum1;
#pragma unroll
        for (int f = 0; f < 16; f++) {
            int col = h * 128 + f * 8 + t2 * 2;
            *(float2*)(out + (size_t)gr0 * 2048 + col) = make_float2(O[f][0] * inv0, O[f][1] * inv0);
            *(float2*)(out + (size_t)gr1 * 2048 + col) = make_float2(O[f][2] * inv1, O[f][3] * inv1);
        }
        __syncthreads();
    }
}

// ---------------------------------------------------------------------------
extern "C" void kernel_launch(void* const* d_in, const int* in_sizes, int n_in,
                              void* d_out, int out_size) {
    (void)in_sizes; (void)n_in; (void)out_size;
    const float* q   = (const float*)d_in[0];
    const float* kc  = (const float*)d_in[1];
    const float* kpe = (const float*)d_in[2];
    const float* wkv = (const float*)d_in[3];
    const float* wuv = (const float*)d_in[4];
    float* out = (float*)d_out;

    conv_all<<<4608, 256>>>(wkv, wuv, kc, kpe);

    cudaFuncSetAttribute(pregemm, cudaFuncAttributeMaxDynamicSharedMemorySize, PG_SMEM);
    cudaFuncSetAttribute(attn,    cudaFuncAttributeMaxDynamicSharedMemorySize, AT_SMEM);

    pregemm<<<dim3(32, 16), 256, PG_SMEM>>>();
    attn<<<296, 128, AT_SMEM>>>(q, out);
}